// round 12
// baseline (speedup 1.0000x reference)
#include <cuda_runtime.h>
#include <cuda_fp16.h>
#include <math.h>
#include <stdint.h>

#define HW    16384
#define Bn    8
#define HIDn  170
#define XSTR  68      // floats per X row = 272B = 17 x 16B granules (conflict-free)
#define WSTR  68

// ---------------- scratch (static device memory) ----------------
__device__ float  g_bufR[Bn * 64 * HW];
__device__ float  g_bufX[Bn * 64 * HW];
__device__ float  g_bufG[Bn * 64 * HW];
__device__ __half g_big1[Bn * 340 * HW];
__device__ __half g_big2[Bn * 340 * HW];
__device__ float  g_attn[Bn * 8 * 64];
__device__ float  g_part[64 * 8 * 80];
__device__ float  g_M[Bn * 64 * 64];

__device__ __forceinline__ float gelu_f(float x) {
    return 0.5f * x * (1.0f + erff(x * 0.70710678118654752f));
}
__device__ __forceinline__ uint16_t bf16b(float x) {
    uint16_t r; asm("cvt.rn.bf16.f32 %0, %1;" : "=h"(r) : "f"(x)); return r;
}
__device__ __forceinline__ uint32_t pk2(uint16_t lo, uint16_t hi) {
    return (uint32_t)lo | ((uint32_t)hi << 16);
}
__device__ __forceinline__ void bsplit(float v, uint16_t& h, uint16_t& l) {
    h = bf16b(v);
    float hf = __uint_as_float((uint32_t)h << 16);
    l = bf16b(v - hf);
}
__device__ __forceinline__ void ldsm4(uint32_t* a, uint32_t addr) {
    asm volatile("ldmatrix.sync.aligned.m8n8.x4.shared.b16 {%0,%1,%2,%3}, [%4];"
        : "=r"(a[0]), "=r"(a[1]), "=r"(a[2]), "=r"(a[3]) : "r"(addr));
}
__device__ __forceinline__ void mma_bf16(float* d, const uint32_t* a, uint32_t b0, uint32_t b1) {
    asm volatile("mma.sync.aligned.m16n8k16.row.col.f32.bf16.bf16.f32 "
        "{%0,%1,%2,%3}, {%4,%5,%6,%7}, {%8,%9}, {%0,%1,%2,%3};"
        : "+f"(d[0]), "+f"(d[1]), "+f"(d[2]), "+f"(d[3])
        : "r"(a[0]), "r"(a[1]), "r"(a[2]), "r"(a[3]), "r"(b0), "r"(b1));
}

// =================================================================
// LN-fused tensor-core conv1x1 (Cin=64, fp32 in), bf16 3-term split,
// fp16 output. 128-px tiles, 3 CTAs/SM. Stages X once, loops
// out-tiles of 64 (Cout up to 384). Warp = 16 px x 64 out.
// =================================================================
__global__ void __launch_bounds__(256, 3)
convtc_kernel(const float* __restrict__ in, const float* __restrict__ addp,
              const float* __restrict__ lnw, const float* __restrict__ lnb,
              const float* __restrict__ wt, __half* __restrict__ out,
              int Cout, int shift)
{
    extern __shared__ float sm[];
    float* Xh   = sm;                         // 128 x 272B rows (8704 floats)
    uint4* BF   = (uint4*)(sm + 128 * XSTR);  // [4kb][8n8][32] uint4 = 16KB
    float* mu_s = sm + 128 * XSTR + 4096;     // [256] partials -> final in [0..127]
    float* rs_s = mu_s + 256;                 // [256]
    float* sg_s = rs_s + 256;                 // [64]
    float* sb_s = sg_s + 64;                  // [64]

    int b = blockIdx.z, p0 = blockIdx.x * 128;
    int tid = threadIdx.x, warp = tid >> 5, lane = tid & 31;
    int px = tid & 127, half = tid >> 7;
    const float* inb = in + (size_t)b * 64 * HW;
    const float* adb = addp ? addp + (size_t)b * 64 * HW : nullptr;

    int p = p0 + px, ip = p;
    if (shift) {
        int hh = ((p >> 7) + shift) & 127, ww = ((p & 127) + shift) & 127;
        ip = (hh << 7) | ww;
    }
    // ---- stage X once (bf16 hi/lo): 2 threads/px, 32 ch each + LN partials ----
    float s_sum = 0.f, s_sq = 0.f;
    char* xrow = (char*)Xh + px * 272;
    #pragma unroll
    for (int j8 = 0; j8 < 4; j8++) {
        uint16_t hb[8], lb[8];
        #pragma unroll
        for (int jj = 0; jj < 8; jj++) {
            int c = half * 32 + j8 * 8 + jj;
            float v = inb[(size_t)c * HW + ip];
            if (adb) v += adb[(size_t)c * HW + ip];
            s_sum += v; s_sq += v * v;
            bsplit(v, hb[jj], lb[jj]);
        }
        *(uint4*)(xrow + half * 64 + j8 * 16) =
            make_uint4(pk2(hb[0], hb[1]), pk2(hb[2], hb[3]), pk2(hb[4], hb[5]), pk2(hb[6], hb[7]));
        *(uint4*)(xrow + 144 + half * 64 + j8 * 16) =
            make_uint4(pk2(lb[0], lb[1]), pk2(lb[2], lb[3]), pk2(lb[4], lb[5]), pk2(lb[6], lb[7]));
    }
    mu_s[tid] = s_sum;
    rs_s[tid] = s_sq;

    int ntile = (Cout + 63) >> 6;
    for (int t = 0; t < ntile; t++) {
        __syncthreads();   // X/partials ready (t=0); BF safe to overwrite (t>0)
        int o0 = t << 6;
        // ---- stage W fragments (bf16 hi/lo, gamma folded) ----
        #pragma unroll
        for (int i = 0; i < 4; i++) {
            int e = i * 256 + tid;
            int kb = e >> 8, rem = e & 255;
            int n8 = rem >> 5, ln2 = rem & 31;
            int g = ln2 >> 2, t2 = ln2 & 3;
            int og = o0 + n8 * 8 + g;
            int kbase = kb * 16;
            float w0 = 0.f, w1 = 0.f, w2 = 0.f, w3 = 0.f;
            if (og < Cout) {
                const float* wr = wt + (size_t)og * 64 + kbase;
                w0 = wr[2 * t2]     * lnw[kbase + 2 * t2];
                w1 = wr[2 * t2 + 1] * lnw[kbase + 2 * t2 + 1];
                w2 = wr[2 * t2 + 8] * lnw[kbase + 2 * t2 + 8];
                w3 = wr[2 * t2 + 9] * lnw[kbase + 2 * t2 + 9];
            }
            uint16_t h0, l0, h1, l1, h2, l2, h3, l3;
            bsplit(w0, h0, l0); bsplit(w1, h1, l1);
            bsplit(w2, h2, l2); bsplit(w3, h3, l3);
            BF[(kb * 8 + n8) * 32 + ln2] =
                make_uint4(pk2(h0, h1), pk2(h2, h3), pk2(l0, l1), pk2(l2, l3));
        }
        if (tid < 64) {
            float sg = 0.f, sb = 0.f;
            int og = o0 + tid;
            if (og < Cout) {
                const float* wr = wt + (size_t)og * 64;
                #pragma unroll 8
                for (int k = 0; k < 64; k++) { sg += wr[k] * lnw[k]; sb += wr[k] * lnb[k]; }
            }
            sg_s[tid] = sg; sb_s[tid] = sb;
        }
        if (t == 0 && tid < 128) {
            float s = mu_s[tid] + mu_s[tid + 128];
            float q = rs_s[tid] + rs_s[tid + 128];
            float m = s * 0.015625f;
            float var = q * 0.015625f - m * m;
            mu_s[tid] = m;
            rs_s[tid] = rsqrtf(fmaxf(var, 0.f) + 1e-5f);
        }
        __syncthreads();

        // ---- tensor GEMM: 4 kb16 steps, 3-term bf16; warp = 16px x 64out ----
        float accD[8][4] = {};
        uint32_t xbase = (uint32_t)__cvta_generic_to_shared(Xh);
        int r = lane & 7, madd8 = (lane >> 3) & 1, gsel = lane >> 4;
        uint32_t abase = xbase + (warp * 16 + r + madd8 * 8) * 272 + gsel * 16;
        #pragma unroll
        for (int kb = 0; kb < 4; kb++) {
            uint32_t Ah0[4], Al0[4];
            uint32_t ah = abase + kb * 32;
            ldsm4(Ah0, ah);
            ldsm4(Al0, ah + 144);
            const uint4* bfk = BF + (size_t)kb * 8 * 32;
            #pragma unroll
            for (int n8 = 0; n8 < 8; n8++) {
                uint4 bv = bfk[n8 * 32 + lane];
                mma_bf16(accD[n8], Ah0, bv.x, bv.y);
                mma_bf16(accD[n8], Al0, bv.x, bv.y);
                mma_bf16(accD[n8], Ah0, bv.z, bv.w);
            }
        }
        // ---- epilogue: LN transform, scattered fp16 stores ----
        int gq = lane >> 2, oq = (lane & 3) * 2;
        int pxa = warp * 16 + gq, pxb = pxa + 8;
        float mua = mu_s[pxa], rsa_ = rs_s[pxa];
        float mub = mu_s[pxb], rsb = rs_s[pxb];
        #pragma unroll
        for (int n8 = 0; n8 < 8; n8++) {
            #pragma unroll
            for (int q = 0; q < 2; q++) {
                int ol = n8 * 8 + oq + q;
                int og = o0 + ol;
                if (og < Cout) {
                    float sg = sg_s[ol], sb = sb_s[ol];
                    float v0 = rsa_ * (accD[n8][q]     - mua * sg) + sb;
                    float v1 = rsb  * (accD[n8][q + 2] - mub * sg) + sb;
                    size_t obase = ((size_t)b * Cout + og) * HW + p0;
                    out[obase + pxa] = __float2half(v0);
                    out[obase + pxb] = __float2half(v1);
                }
            }
        }
    }
}

// =================================================================
// gated tensor-core conv (fp16 in, Cin=170 phys 340), bf16 3-term,
// fp32 out + resid, scattered epilogue (round-9 form).
// =================================================================
__global__ void __launch_bounds__(256, 3)
convgate_kernel(const __half* __restrict__ in, const float* __restrict__ wt,
                float* __restrict__ out, const float* __restrict__ resid)
{
    extern __shared__ float sm[];
    float* Xh = sm;                          // 128 x 272B rows
    uint4* BF = (uint4*)(sm + 128 * XSTR);   // [4kb][8n8][32] uint4

    int b = blockIdx.z, p0 = blockIdx.x * 128;
    int tid = threadIdx.x, warp = tid >> 5, lane = tid & 31;
    int px = tid & 127, half = tid >> 7;
    int ip = p0 + px;
    const __half* inb = in + (size_t)b * 340 * HW;

    float acc[8][4] = {};
    const int kbs16[3] = {4, 4, 3};
    for (int ch = 0; ch < 3; ch++) {
        if (ch) __syncthreads();
        int c0 = ch * 64;
        int nkb = kbs16[ch];
        // ---- stage X: 2 threads/px, 32 channels each ----
        char* xrow = (char*)Xh + px * 272;
        #pragma unroll
        for (int j8 = 0; j8 < 4; j8++) {
            uint16_t hb[8], lb[8];
            #pragma unroll
            for (int jj = 0; jj < 8; jj++) {
                int c = c0 + half * 32 + j8 * 8 + jj;
                float v = 0.f;
                if (c < HIDn) {
                    float a = __half2float(inb[(size_t)c * HW + ip]);
                    float g = __half2float(inb[(size_t)(c + HIDn) * HW + ip]);
                    v = gelu_f(a) * g;
                }
                bsplit(v, hb[jj], lb[jj]);
            }
            *(uint4*)(xrow + half * 64 + j8 * 16) =
                make_uint4(pk2(hb[0], hb[1]), pk2(hb[2], hb[3]), pk2(hb[4], hb[5]), pk2(hb[6], hb[7]));
            *(uint4*)(xrow + 144 + half * 64 + j8 * 16) =
                make_uint4(pk2(lb[0], lb[1]), pk2(lb[2], lb[3]), pk2(lb[4], lb[5]), pk2(lb[6], lb[7]));
        }
        // ---- stage BF ----
        int tot = nkb * 256;
        for (int e = tid; e < tot; e += 256) {
            int kb = e >> 8, rem = e & 255;
            int n8 = rem >> 5, ln2 = rem & 31;
            int g = ln2 >> 2, t2 = ln2 & 3;
            int o = n8 * 8 + g;
            int kbase = c0 + kb * 16;
            int k0 = kbase + 2 * t2, k1 = k0 + 1, k2 = kbase + 2 * t2 + 8, k3 = k2 + 1;
            float w0 = (k0 < HIDn) ? wt[(size_t)o * HIDn + k0] : 0.f;
            float w1 = (k1 < HIDn) ? wt[(size_t)o * HIDn + k1] : 0.f;
            float w2 = (k2 < HIDn) ? wt[(size_t)o * HIDn + k2] : 0.f;
            float w3 = (k3 < HIDn) ? wt[(size_t)o * HIDn + k3] : 0.f;
            uint16_t h0, l0, h1, l1, h2, l2, h3, l3;
            bsplit(w0, h0, l0); bsplit(w1, h1, l1);
            bsplit(w2, h2, l2); bsplit(w3, h3, l3);
            BF[(kb * 8 + n8) * 32 + ln2] =
                make_uint4(pk2(h0, h1), pk2(h2, h3), pk2(l0, l1), pk2(l2, l3));
        }
        __syncthreads();
        // ---- GEMM: warp = 16 px x 64 out ----
        uint32_t xbase = (uint32_t)__cvta_generic_to_shared(Xh);
        int r = lane & 7, madd8 = (lane >> 3) & 1, gsel = lane >> 4;
        uint32_t abase = xbase + (warp * 16 + r + madd8 * 8) * 272 + gsel * 16;
        #pragma unroll
        for (int kb = 0; kb < 4; kb++) {
            if (kb >= nkb) break;
            uint32_t Ah0[4], Al0[4];
            uint32_t ah = abase + kb * 32;
            ldsm4(Ah0, ah);
            ldsm4(Al0, ah + 144);
            const uint4* bfk = BF + (size_t)kb * 8 * 32;
            #pragma unroll
            for (int n8 = 0; n8 < 8; n8++) {
                uint4 bv = bfk[n8 * 32 + lane];
                mma_bf16(acc[n8], Ah0, bv.x, bv.y);
                mma_bf16(acc[n8], Al0, bv.x, bv.y);
                mma_bf16(acc[n8], Ah0, bv.z, bv.w);
            }
        }
    }
    // epilogue: + resid (fp32 out, scattered)
    int gq = lane >> 2, oq = (lane & 3) * 2;
    int pxa = warp * 16 + gq, pxb = pxa + 8;
    #pragma unroll
    for (int n8 = 0; n8 < 8; n8++) {
        #pragma unroll
        for (int q = 0; q < 2; q++) {
            int og = n8 * 8 + oq + q;
            size_t obase = ((size_t)b * 64 + og) * HW + p0;
            out[obase + pxa] = acc[n8][q]     + resid[obase + pxa];
            out[obase + pxb] = acc[n8][q + 2] + resid[obase + pxb];
        }
    }
}

// ---------------- depthwise 3x3 conv, fp16 I/O, 8 px/thread ----------------
__global__ void dwconv_kernel(const __half* __restrict__ in, const float* __restrict__ wt,
                              __half* __restrict__ out, int Ch)
{
    int c = blockIdx.y, b = blockIdx.z;
    int p = (blockIdx.x * 256 + threadIdx.x) << 3;
    int h = p >> 7, w0 = p & 127;
    const __half* ib = in + ((size_t)b * Ch + c) * HW;
    const float* wc = wt + c * 9;
    float acc[8] = {0.f,0.f,0.f,0.f,0.f,0.f,0.f,0.f};
    #pragma unroll
    for (int dy = -1; dy <= 1; dy++) {
        int hh = h + dy;
        if ((unsigned)hh > 127u) continue;
        const __half* row = ib + (hh << 7);
        uint4 mraw = *(const uint4*)(row + w0);
        const __half2* m2 = (const __half2*)&mraw;
        float r[10];
        r[0] = (w0 > 0)   ? __half2float(row[w0 - 1]) : 0.f;
        #pragma unroll
        for (int k = 0; k < 4; k++) {
            float2 f = __half22float2(m2[k]);
            r[1 + 2 * k] = f.x; r[2 + 2 * k] = f.y;
        }
        r[9] = (w0 < 120) ? __half2float(row[w0 + 8]) : 0.f;
        float wa = wc[(dy + 1) * 3 + 0], wb = wc[(dy + 1) * 3 + 1], wcc = wc[(dy + 1) * 3 + 2];
        #pragma unroll
        for (int j = 0; j < 8; j++)
            acc[j] += wa * r[j] + wb * r[j + 1] + wcc * r[j + 2];
    }
    __half2 o2[4];
    #pragma unroll
    for (int k = 0; k < 4; k++) o2[k] = __floats2half2_rn(acc[2 * k], acc[2 * k + 1]);
    *(uint4*)(out + ((size_t)b * Ch + c) * HW + p) = *(uint4*)o2;
}

// =================================================================
// RSA window attention (fp16 qkv in) + fused proj conv + inverse roll
// =================================================================
__global__ void __launch_bounds__(256, 3)
rsa_attn_kernel(const __half* __restrict__ qkv, const float* __restrict__ pw,
                float* __restrict__ out, const float* __restrict__ temp)
{
    extern __shared__ float sm[];
    float* A   = sm;
    float* B   = sm + 64 * WSTR;
    float* C   = sm + 2 * 64 * WSTR;
    float* Pw  = sm + 3 * 64 * WSTR;
    float* inv = Pw + 64 * WSTR;
    int blk = blockIdx.x;
    int b = blk >> 8, win = blk & 255;
    int wy = win >> 4, wx = win & 15;
    int tid = threadIdx.x;
    size_t qbase = (size_t)b * 192 * HW;

    for (int e = tid; e < 4096; e += 256) {
        int p = e & 63, c = e >> 6;
        int gp = (((wy << 3) + (p >> 3)) << 7) | ((wx << 3) + (p & 7));
        A[p * WSTR + c] = __half2float(qkv[qbase + c * HW + gp]);
        B[p * WSTR + c] = __half2float(qkv[qbase + (64 + c) * HW + gp]);
        Pw[(e & 63) * WSTR + (e >> 6)] = pw[e];
    }
    __syncthreads();
    if (tid < 64) {
        int p = tid;
        float nq = 0.f, nk = 0.f;
        #pragma unroll
        for (int c = 0; c < 64; c++) {
            float a = A[p * WSTR + c]; nq += a * a;
            float bb = B[p * WSTR + c]; nk += bb * bb;
        }
        inv[p] = 1.0f / (fmaxf(sqrtf(nq), 1e-12f) * fmaxf(sqrtf(nk), 1e-12f));
    }
    __syncthreads();
    for (int e4 = tid; e4 < 1024; e4 += 256) {
        int p = e4 >> 4, c4 = e4 & 15;
        float iv = inv[p];
        float4 v = ((float4*)B)[p * (WSTR / 4) + c4];
        v.x *= iv; v.y *= iv; v.z *= iv; v.w *= iv;
        ((float4*)B)[p * (WSTR / 4) + c4] = v;
    }
    __syncthreads();
    float tscale = temp[0];
    {   // GEMM1: attn
        int c0 = (tid >> 4) << 2, d0 = (tid & 15) << 2;
        float s[4][4] = {};
        #pragma unroll 4
        for (int p = 0; p < 64; p++) {
            float4 qv = *(const float4*)(A + p * WSTR + c0);
            float4 kv = *(const float4*)(B + p * WSTR + d0);
            float qr[4] = {qv.x, qv.y, qv.z, qv.w};
            float kr[4] = {kv.x, kv.y, kv.z, kv.w};
            #pragma unroll
            for (int i = 0; i < 4; i++)
                #pragma unroll
                for (int j = 0; j < 4; j++) s[i][j] += qr[i] * kr[j];
        }
        #pragma unroll
        for (int i = 0; i < 4; i++)
            *(float4*)(C + (c0 + i) * WSTR + d0) =
                make_float4(fmaxf(0.f, tscale * s[i][0]), fmaxf(0.f, tscale * s[i][1]),
                            fmaxf(0.f, tscale * s[i][2]), fmaxf(0.f, tscale * s[i][3]));
    }
    __syncthreads();
    for (int e = tid; e < 4096; e += 256) {
        int p = e & 63, c = e >> 6;
        int gp = (((wy << 3) + (p >> 3)) << 7) | ((wx << 3) + (p & 7));
        A[c * WSTR + p] = __half2float(qkv[qbase + (128 + c) * HW + gp]);
    }
    __syncthreads();
    {   // GEMM2: out[d][p]
        int p0 = (tid >> 4) << 2, d0 = (tid & 15) << 2;
        float s[4][4] = {};
        #pragma unroll 4
        for (int c = 0; c < 64; c++) {
            float4 vv = *(const float4*)(A + c * WSTR + p0);
            float4 av = *(const float4*)(C + c * WSTR + d0);
            float vr[4] = {vv.x, vv.y, vv.z, vv.w};
            float ar[4] = {av.x, av.y, av.z, av.w};
            #pragma unroll
            for (int i = 0; i < 4; i++)
                #pragma unroll
                for (int j = 0; j < 4; j++) s[i][j] += vr[i] * ar[j];
        }
        #pragma unroll
        for (int j = 0; j < 4; j++)
            *(float4*)(B + (d0 + j) * WSTR + p0) = make_float4(s[0][j], s[1][j], s[2][j], s[3][j]);
    }
    __syncthreads();
    {   // GEMM3: proj
        int o0 = (tid >> 4) << 2, p0 = (tid & 15) << 2;
        float s[4][4] = {};
        #pragma unroll 4
        for (int d = 0; d < 64; d++) {
            float4 wv = *(const float4*)(Pw + d * WSTR + o0);
            float4 bv = *(const float4*)(B + d * WSTR + p0);
            float wr[4] = {wv.x, wv.y, wv.z, wv.w};
            float br[4] = {bv.x, bv.y, bv.z, bv.w};
            #pragma unroll
            for (int i = 0; i < 4; i++)
                #pragma unroll
                for (int j = 0; j < 4; j++) s[i][j] += wr[i] * br[j];
        }
        #pragma unroll
        for (int i = 0; i < 4; i++)
            *(float4*)(C + (o0 + i) * WSTR + p0) = make_float4(s[i][0], s[i][1], s[i][2], s[i][3]);
    }
    __syncthreads();
    size_t obase = (size_t)b * 64 * HW;
    for (int e = tid; e < 4096; e += 256) {
        int p = e & 63, o = e >> 6;
        int gh = (((wy << 3) + (p >> 3)) + 4) & 127;
        int gw = (((wx << 3) + (p & 7)) + 4) & 127;
        out[obase + o * HW + (gh << 7) + gw] = C[o * WSTR + p];
    }
}

// ---------------- GSA: partial Gram sums (fp16 qkv in) ---------------------------
__global__ void gsa_attn_part(const __half* __restrict__ qkv, float* __restrict__ part)
{
    __shared__ float red[8][80];
    int bh = blockIdx.y;
    int b = bh >> 3, hd = bh & 7;
    int chunk = blockIdx.x;
    int tid = threadIdx.x;
    const __half* qb = qkv + ((size_t)b * 192 + hd * 8) * HW;
    const __half* kb = qkv + ((size_t)b * 192 + 64 + hd * 8) * HW;
    float dot[8][8] = {};
    float qn[8] = {}, kn[8] = {};
    int n0 = chunk * 2048;
    for (int n = n0 + tid; n < n0 + 2048; n += 256) {
        float qv[8], kv[8];
        #pragma unroll
        for (int i = 0; i < 8; i++) {
            qv[i] = __half2float(qb[i * HW + n]);
            kv[i] = __half2float(kb[i * HW + n]);
        }
        #pragma unroll
        for (int i = 0; i < 8; i++) { qn[i] += qv[i] * qv[i]; kn[i] += kv[i] * kv[i]; }
        #pragma unroll
        for (int i = 0; i < 8; i++)
            #pragma unroll
            for (int j = 0; j < 8; j++) dot[i][j] += qv[i] * kv[j];
    }
    int lane = tid & 31, w = tid >> 5;
    #pragma unroll
    for (int i = 0; i < 8; i++)
        #pragma unroll
        for (int j = 0; j < 8; j++) {
            float v = dot[i][j];
            #pragma unroll
            for (int off = 16; off; off >>= 1) v += __shfl_xor_sync(0xffffffffu, v, off);
            if (lane == 0) red[w][i * 8 + j] = v;
        }
    #pragma unroll
    for (int i = 0; i < 8; i++) {
        float v = qn[i];
        #pragma unroll
        for (int off = 16; off; off >>= 1) v += __shfl_xor_sync(0xffffffffu, v, off);
        if (lane == 0) red[w][64 + i] = v;
        float u = kn[i];
        #pragma unroll
        for (int off = 16; off; off >>= 1) u += __shfl_xor_sync(0xffffffffu, u, off);
        if (lane == 0) red[w][72 + i] = u;
    }
    __syncthreads();
    if (tid < 80) {
        float s = 0.f;
        #pragma unroll
        for (int w2 = 0; w2 < 8; w2++) s += red[w2][tid];
        part[((size_t)bh * 8 + chunk) * 80 + tid] = s;
    }
}

__global__ void gsa_attn_final(const float* __restrict__ part, float* __restrict__ attn,
                               const float* __restrict__ temp)
{
    __shared__ float fin[80];
    int bh = blockIdx.x, tid = threadIdx.x;
    if (tid < 80) {
        float s = 0.f;
        #pragma unroll
        for (int c = 0; c < 8; c++) s += part[((size_t)bh * 8 + c) * 80 + tid];
        fin[tid] = s;
    }
    __syncthreads();
    if (tid < 64) {
        int c = tid >> 3, d = tid & 7;
        float nq = fmaxf(sqrtf(fin[64 + c]), 1e-12f);
        float nk = fmaxf(sqrtf(fin[72 + d]), 1e-12f);
        attn[(size_t)bh * 64 + tid] = fmaxf(0.f, temp[0] * fin[tid] / (nq * nk));
    }
}

// ---------------- GSA: fold proj into attention matrix -------------------------
__global__ void gsa_makeM(const float* __restrict__ attn, const float* __restrict__ pw,
                          float* __restrict__ M)
{
    __shared__ float at[512];
    int b = blockIdx.x, tid = threadIdx.x;
    for (int e = tid; e < 512; e += 256) at[e] = attn[(size_t)b * 512 + e];
    __syncthreads();
    for (int t = 0; t < 16; t++) {
        int e = t * 256 + tid;
        int o = e >> 6, chp = e & 63;
        int hd = chp >> 3, d = chp & 7;
        float s = 0.f;
        #pragma unroll
        for (int c = 0; c < 8; c++)
            s += pw[(size_t)o * 64 + c * 8 + hd] * at[hd * 64 + c * 8 + d];
        M[(size_t)b * 4096 + e] = s;
    }
}

// ---------------- GSA: out = M @ v (fp16 v in, proj included) --------------------
__global__ void gsa_mv_kernel(const __half* __restrict__ qkv, const float* __restrict__ M,
                              float* __restrict__ out)
{
    __shared__ float Ms[4096];
    int b = blockIdx.y, tid = threadIdx.x;
    for (int e = tid; e < 4096; e += 256) Ms[e] = M[(size_t)b * 4096 + e];
    __syncthreads();
    int n = blockIdx.x * 256 + tid;
    const __half* vb = qkv + ((size_t)b * 192 + 128) * HW + n;
    float* ob = out + (size_t)b * 64 * HW + n;
    float vv[64];
    #pragma unroll
    for (int c = 0; c < 64; c++) vv[c] = __half2float(vb[(size_t)c * HW]);
    #pragma unroll
    for (int og = 0; og < 8; og++) {
        float acc[8] = {0.f,0.f,0.f,0.f,0.f,0.f,0.f,0.f};
        #pragma unroll
        for (int c = 0; c < 64; c++) {
            float v = vv[c];
            #pragma unroll
            for (int j = 0; j < 8; j++) acc[j] += Ms[(og * 8 + j) * 64 + c] * v;
        }
        #pragma unroll
        for (int j = 0; j < 8; j++) ob[(size_t)(og * 8 + j) * HW] = acc[j];
    }
}

// ---------------- launch ---------------------------------------------------------
extern "C" void kernel_launch(void* const* d_in, const int* in_sizes, int n_in,
                              void* d_out, int out_size)
{
    const float* x         = (const float*)d_in[0];
    const float* ln_s0_w   = (const float*)d_in[1];
    const float* ln_s0_b   = (const float*)d_in[2];
    const float* ln_s2_w   = (const float*)d_in[3];
    const float* ln_s2_b   = (const float*)d_in[4];
    const float* rsa_qkv_w = (const float*)d_in[5];
    const float* rsa_dw_w  = (const float*)d_in[6];
    const float* rsa_proj_w= (const float*)d_in[7];
    const float* rsa_temp  = (const float*)d_in[8];
    const float* ffs_in_w  = (const float*)d_in[9];
    const float* ffs_dw_w  = (const float*)d_in[10];
    const float* ffs_out_w = (const float*)d_in[11];
    const float* ln_c0_w   = (const float*)d_in[12];
    const float* ln_c0_b   = (const float*)d_in[13];
    const float* ln_c2_w   = (const float*)d_in[14];
    const float* ln_c2_b   = (const float*)d_in[15];
    const float* gsa_qkv_w = (const float*)d_in[16];
    const float* gsa_dw_w  = (const float*)d_in[17];
    const float* gsa_proj_w= (const float*)d_in[18];
    const float* gsa_temp  = (const float*)d_in[19];
    const float* ffc_in_w  = (const float*)d_in[20];
    const float* ffc_dw_w  = (const float*)d_in[21];
    const float* ffc_out_w = (const float*)d_in[22];
    float* outp = (float*)d_out;

    float *bufR, *bufX, *bufG, *attnb, *partb, *Mb;
    __half *big1, *big2;
    cudaGetSymbolAddress((void**)&bufR,  g_bufR);
    cudaGetSymbolAddress((void**)&bufX,  g_bufX);
    cudaGetSymbolAddress((void**)&bufG,  g_bufG);
    cudaGetSymbolAddress((void**)&big1,  g_big1);
    cudaGetSymbolAddress((void**)&big2,  g_big2);
    cudaGetSymbolAddress((void**)&attnb, g_attn);
    cudaGetSymbolAddress((void**)&partb, g_part);
    cudaGetSymbolAddress((void**)&Mb,    g_M);

    // convtc: X(8704) + BF(4096) + mu/rs(512) + sg/sb(128) = 13440 floats = 53760 B
    const int ctc_smem = (128 * XSTR + 4096 + 256 + 256 + 64 + 64) * (int)sizeof(float);
    const int cg_smem  = (128 * XSTR + 4096) * (int)sizeof(float);   // 51200
    const int rsa_smem = (4 * 64 * WSTR + 64) * (int)sizeof(float);
    cudaFuncSetAttribute(convtc_kernel, cudaFuncAttributeMaxDynamicSharedMemorySize, ctc_smem);
    cudaFuncSetAttribute(convgate_kernel, cudaFuncAttributeMaxDynamicSharedMemorySize, cg_smem);
    cudaFuncSetAttribute(rsa_attn_kernel, cudaFuncAttributeMaxDynamicSharedMemorySize, rsa_smem);

    // ---- stage 1: RSA + spatial FFN ----
    convtc_kernel<<<dim3(128, 1, Bn), 256, ctc_smem>>>(x, nullptr, ln_s0_w, ln_s0_b, rsa_qkv_w, big1, 192, 4);
    dwconv_kernel<<<dim3(8, 192, Bn), 256>>>(big1, rsa_dw_w, big2, 192);
    rsa_attn_kernel<<<Bn * 256, 256, rsa_smem>>>(big2, rsa_proj_w, bufR, rsa_temp);
    convtc_kernel<<<dim3(128, 1, Bn), 256, ctc_smem>>>(bufR, x, ln_s2_w, ln_s2_b, ffs_in_w, big1, 340, 0);
    dwconv_kernel<<<dim3(8, 340, Bn), 256>>>(big1, ffs_dw_w, big2, 340);
    convgate_kernel<<<dim3(128, 1, Bn), 256, cg_smem>>>(big2, ffs_out_w, bufX, bufR);

    // ---- stage 2: GSA + channel FFN ----
    convtc_kernel<<<dim3(128, 1, Bn), 256, ctc_smem>>>(bufX, nullptr, ln_c0_w, ln_c0_b, gsa_qkv_w, big1, 192, 0);
    dwconv_kernel<<<dim3(8, 192, Bn), 256>>>(big1, gsa_dw_w, big2, 192);
    gsa_attn_part<<<dim3(8, 64), 256>>>(big2, partb);
    gsa_attn_final<<<64, 128>>>(partb, attnb, gsa_temp);
    gsa_makeM<<<Bn, 256>>>(attnb, gsa_proj_w, Mb);
    gsa_mv_kernel<<<dim3(64, Bn), 256>>>(big2, Mb, bufG);
    convtc_kernel<<<dim3(128, 1, Bn), 256, ctc_smem>>>(bufG, bufX, ln_c2_w, ln_c2_b, ffc_in_w, big1, 340, 0);
    dwconv_kernel<<<dim3(8, 340, Bn), 256>>>(big1, ffc_dw_w, big2, 340);
    convgate_kernel<<<dim3(128, 1, Bn), 256, cg_smem>>>(big2, ffc_out_w, outp, bufG);
}

// round 13
// speedup vs baseline: 1.1471x; 1.1471x over previous
#include <cuda_runtime.h>
#include <cuda_fp16.h>
#include <math.h>
#include <stdint.h>

#define HW    16384
#define Bn    8
#define HIDn  170
#define XSTR  68      // floats per X row = 272B = 17 x 16B granules (conflict-free)
#define WSTR  68

// ---------------- scratch (static device memory) ----------------
__device__ float  g_bufR[Bn * 64 * HW];
__device__ float  g_bufX[Bn * 64 * HW];
__device__ float  g_bufG[Bn * 64 * HW];
__device__ __half g_big1[Bn * 340 * HW];
__device__ __half g_big2[Bn * 340 * HW];
__device__ float  g_attn[Bn * 8 * 64];
__device__ float  g_part[64 * 8 * 80];
__device__ float  g_M[Bn * 64 * 64];

__device__ __forceinline__ float gelu_f(float x) {
    return 0.5f * x * (1.0f + erff(x * 0.70710678118654752f));
}
__device__ __forceinline__ uint16_t bf16b(float x) {
    uint16_t r; asm("cvt.rn.bf16.f32 %0, %1;" : "=h"(r) : "f"(x)); return r;
}
__device__ __forceinline__ uint32_t pk2(uint16_t lo, uint16_t hi) {
    return (uint32_t)lo | ((uint32_t)hi << 16);
}
__device__ __forceinline__ void bsplit(float v, uint16_t& h, uint16_t& l) {
    h = bf16b(v);
    float hf = __uint_as_float((uint32_t)h << 16);
    l = bf16b(v - hf);
}
__device__ __forceinline__ void ldsm4(uint32_t* a, uint32_t addr) {
    asm volatile("ldmatrix.sync.aligned.m8n8.x4.shared.b16 {%0,%1,%2,%3}, [%4];"
        : "=r"(a[0]), "=r"(a[1]), "=r"(a[2]), "=r"(a[3]) : "r"(addr));
}
__device__ __forceinline__ void mma_bf16(float* d, const uint32_t* a, uint32_t b0, uint32_t b1) {
    asm volatile("mma.sync.aligned.m16n8k16.row.col.f32.bf16.bf16.f32 "
        "{%0,%1,%2,%3}, {%4,%5,%6,%7}, {%8,%9}, {%0,%1,%2,%3};"
        : "+f"(d[0]), "+f"(d[1]), "+f"(d[2]), "+f"(d[3])
        : "r"(a[0]), "r"(a[1]), "r"(a[2]), "r"(a[3]), "r"(b0), "r"(b1));
}

// =================================================================
// LN-fused tensor-core conv1x1 (Cin=64, fp32 in), bf16 3-term split,
// fp16 output. 256-px tiles, 2 CTAs/SM, warp = 32px x 64out.
// Double-buffered W staging: one barrier per out-tile; staging of
// tile t+1 overlaps GEMM/epilogue of tile t.
// =================================================================
__global__ void __launch_bounds__(256, 2)
convtc_kernel(const float* __restrict__ in, const float* __restrict__ addp,
              const float* __restrict__ lnw, const float* __restrict__ lnb,
              const float* __restrict__ wt, __half* __restrict__ out,
              int Cout, int shift)
{
    extern __shared__ float sm[];
    float* Xh   = sm;                         // 256 x 272B rows (17408 floats)
    uint4* BF   = (uint4*)(sm + 256 * XSTR);  // 2 x [4kb][8n8][32] uint4 = 32KB
    float* mu_s = sm + 256 * XSTR + 8192;     // [256]
    float* rs_s = mu_s + 256;                 // [256]
    float* sg_s = rs_s + 256;                 // [128] (2 slots of 64)
    float* sb_s = sg_s + 128;                 // [128]

    int b = blockIdx.z, p0 = blockIdx.x * 256;
    int tid = threadIdx.x, warp = tid >> 5, lane = tid & 31;
    const float* inb = in + (size_t)b * 64 * HW;
    const float* adb = addp ? addp + (size_t)b * 64 * HW : nullptr;

    int p = p0 + tid, ip = p;
    if (shift) {
        int hh = ((p >> 7) + shift) & 127, ww = ((p & 127) + shift) & 127;
        ip = (hh << 7) | ww;
    }
    // ---- stage X once (bf16 hi/lo) + LN stats ----
    float s_sum = 0.f, s_sq = 0.f;
    char* xrow = (char*)Xh + tid * 272;
    #pragma unroll
    for (int j8 = 0; j8 < 8; j8++) {
        uint16_t hb[8], lb[8];
        #pragma unroll
        for (int jj = 0; jj < 8; jj++) {
            int c = j8 * 8 + jj;
            float v = inb[(size_t)c * HW + ip];
            if (adb) v += adb[(size_t)c * HW + ip];
            s_sum += v; s_sq += v * v;
            bsplit(v, hb[jj], lb[jj]);
        }
        *(uint4*)(xrow + j8 * 16) =
            make_uint4(pk2(hb[0], hb[1]), pk2(hb[2], hb[3]), pk2(hb[4], hb[5]), pk2(hb[6], hb[7]));
        *(uint4*)(xrow + 144 + j8 * 16) =
            make_uint4(pk2(lb[0], lb[1]), pk2(lb[2], lb[3]), pk2(lb[4], lb[5]), pk2(lb[6], lb[7]));
    }
    {
        float m = s_sum * 0.015625f;
        float var = s_sq * 0.015625f - m * m;
        mu_s[tid] = m;
        rs_s[tid] = rsqrtf(fmaxf(var, 0.f) + 1e-5f);
    }

    int ntile = (Cout + 63) >> 6;

    // ---- W staging lambda-equivalent (macro via inline code blocks) ----
    // stage tile `tt` weights into BF slot `sl` and sg/sb slot `sl`
    #define STAGE_W(tt, sl)                                                              \
    {                                                                                    \
        int o0s = (tt) << 6;                                                             \
        uint4* bfs = BF + (size_t)(sl) * 1024;                                           \
        _Pragma("unroll")                                                                \
        for (int i = 0; i < 4; i++) {                                                    \
            int e = i * 256 + tid;                                                       \
            int kb = e >> 8, rem = e & 255;                                              \
            int n8 = rem >> 5, ln2 = rem & 31;                                           \
            int g = ln2 >> 2, t2 = ln2 & 3;                                              \
            int og = o0s + n8 * 8 + g;                                                   \
            int kbase = kb * 16;                                                         \
            float w0 = 0.f, w1 = 0.f, w2 = 0.f, w3 = 0.f;                                \
            if (og < Cout) {                                                             \
                const float* wr = wt + (size_t)og * 64 + kbase;                          \
                w0 = wr[2 * t2]     * lnw[kbase + 2 * t2];                               \
                w1 = wr[2 * t2 + 1] * lnw[kbase + 2 * t2 + 1];                           \
                w2 = wr[2 * t2 + 8] * lnw[kbase + 2 * t2 + 8];                           \
                w3 = wr[2 * t2 + 9] * lnw[kbase + 2 * t2 + 9];                           \
            }                                                                            \
            uint16_t h0, l0, h1, l1, h2, l2, h3, l3;                                     \
            bsplit(w0, h0, l0); bsplit(w1, h1, l1);                                      \
            bsplit(w2, h2, l2); bsplit(w3, h3, l3);                                      \
            bfs[(kb * 8 + n8) * 32 + ln2] =                                              \
                make_uint4(pk2(h0, h1), pk2(h2, h3), pk2(l0, l1), pk2(l2, l3));          \
        }                                                                                \
        if (tid < 64) {                                                                  \
            float sg = 0.f, sb = 0.f;                                                    \
            int og = o0s + tid;                                                          \
            if (og < Cout) {                                                             \
                const float* wr = wt + (size_t)og * 64;                                  \
                _Pragma("unroll 8")                                                      \
                for (int k = 0; k < 64; k++) { sg += wr[k] * lnw[k]; sb += wr[k] * lnb[k]; } \
            }                                                                            \
            sg_s[(sl) * 64 + tid] = sg; sb_s[(sl) * 64 + tid] = sb;                      \
        }                                                                                \
    }

    STAGE_W(0, 0);
    __syncthreads();

    for (int t = 0; t < ntile; t++) {
        int slot = t & 1;
        int o0 = t << 6;
        // ---- tensor GEMM: 4 kb16 steps, 3-term bf16 ----
        float accD[2][8][4] = {};
        uint32_t xbase = (uint32_t)__cvta_generic_to_shared(Xh);
        int r = lane & 7, madd8 = (lane >> 3) & 1, gsel = lane >> 4;
        uint32_t abase = xbase + (warp * 32 + r + madd8 * 8) * 272 + gsel * 16;
        const uint4* bfb = BF + (size_t)slot * 1024;
        #pragma unroll
        for (int kb = 0; kb < 4; kb++) {
            uint32_t Ah0[4], Ah1[4], Al0[4], Al1[4];
            uint32_t ah = abase + kb * 32;
            ldsm4(Ah0, ah);
            ldsm4(Ah1, ah + 16 * 272);
            ldsm4(Al0, ah + 144);
            ldsm4(Al1, ah + 144 + 16 * 272);
            const uint4* bfk = bfb + (size_t)kb * 8 * 32;
            #pragma unroll
            for (int n8 = 0; n8 < 8; n8++) {
                uint4 bv = bfk[n8 * 32 + lane];
                mma_bf16(accD[0][n8], Ah0, bv.x, bv.y);
                mma_bf16(accD[0][n8], Al0, bv.x, bv.y);
                mma_bf16(accD[0][n8], Ah0, bv.z, bv.w);
                mma_bf16(accD[1][n8], Ah1, bv.x, bv.y);
                mma_bf16(accD[1][n8], Al1, bv.x, bv.y);
                mma_bf16(accD[1][n8], Ah1, bv.z, bv.w);
            }
        }
        // ---- stage NEXT tile's weights into the other buffer (overlaps epilogue) ----
        if (t + 1 < ntile) STAGE_W(t + 1, 1 - slot);
        // ---- epilogue (LN transform, scattered fp16 stores) ----
        int gq = lane >> 2, oq = (lane & 3) * 2;
        const float* sgp = sg_s + slot * 64;
        const float* sbp = sb_s + slot * 64;
        #pragma unroll
        for (int tt = 0; tt < 2; tt++) {
            int pxa = warp * 32 + tt * 16 + gq;
            int pxb = pxa + 8;
            float mua = mu_s[pxa], rsa_ = rs_s[pxa];
            float mub = mu_s[pxb], rsb = rs_s[pxb];
            #pragma unroll
            for (int n8 = 0; n8 < 8; n8++) {
                #pragma unroll
                for (int q = 0; q < 2; q++) {
                    int ol = n8 * 8 + oq + q;
                    int og = o0 + ol;
                    if (og < Cout) {
                        float sg = sgp[ol], sb = sbp[ol];
                        float v0 = rsa_ * (accD[tt][n8][q]     - mua * sg) + sb;
                        float v1 = rsb  * (accD[tt][n8][q + 2] - mub * sg) + sb;
                        size_t obase = ((size_t)b * Cout + og) * HW + p0;
                        out[obase + pxa] = __float2half(v0);
                        out[obase + pxb] = __float2half(v1);
                    }
                }
            }
        }
        __syncthreads();
    }
    #undef STAGE_W
}

// =================================================================
// gated tensor-core conv (fp16 in, Cin=170 phys 340), bf16 3-term,
// fp32 out + resid, scattered epilogue (round-9 form).
// =================================================================
__global__ void __launch_bounds__(256, 3)
convgate_kernel(const __half* __restrict__ in, const float* __restrict__ wt,
                float* __restrict__ out, const float* __restrict__ resid)
{
    extern __shared__ float sm[];
    float* Xh = sm;                          // 128 x 272B rows
    uint4* BF = (uint4*)(sm + 128 * XSTR);   // [4kb][8n8][32] uint4

    int b = blockIdx.z, p0 = blockIdx.x * 128;
    int tid = threadIdx.x, warp = tid >> 5, lane = tid & 31;
    int px = tid & 127, half = tid >> 7;
    int ip = p0 + px;
    const __half* inb = in + (size_t)b * 340 * HW;

    float acc[8][4] = {};
    const int kbs16[3] = {4, 4, 3};
    for (int ch = 0; ch < 3; ch++) {
        if (ch) __syncthreads();
        int c0 = ch * 64;
        int nkb = kbs16[ch];
        // ---- stage X: 2 threads/px, 32 channels each ----
        char* xrow = (char*)Xh + px * 272;
        #pragma unroll
        for (int j8 = 0; j8 < 4; j8++) {
            uint16_t hb[8], lb[8];
            #pragma unroll
            for (int jj = 0; jj < 8; jj++) {
                int c = c0 + half * 32 + j8 * 8 + jj;
                float v = 0.f;
                if (c < HIDn) {
                    float a = __half2float(inb[(size_t)c * HW + ip]);
                    float g = __half2float(inb[(size_t)(c + HIDn) * HW + ip]);
                    v = gelu_f(a) * g;
                }
                bsplit(v, hb[jj], lb[jj]);
            }
            *(uint4*)(xrow + half * 64 + j8 * 16) =
                make_uint4(pk2(hb[0], hb[1]), pk2(hb[2], hb[3]), pk2(hb[4], hb[5]), pk2(hb[6], hb[7]));
            *(uint4*)(xrow + 144 + half * 64 + j8 * 16) =
                make_uint4(pk2(lb[0], lb[1]), pk2(lb[2], lb[3]), pk2(lb[4], lb[5]), pk2(lb[6], lb[7]));
        }
        // ---- stage BF ----
        int tot = nkb * 256;
        for (int e = tid; e < tot; e += 256) {
            int kb = e >> 8, rem = e & 255;
            int n8 = rem >> 5, ln2 = rem & 31;
            int g = ln2 >> 2, t2 = ln2 & 3;
            int o = n8 * 8 + g;
            int kbase = c0 + kb * 16;
            int k0 = kbase + 2 * t2, k1 = k0 + 1, k2 = kbase + 2 * t2 + 8, k3 = k2 + 1;
            float w0 = (k0 < HIDn) ? wt[(size_t)o * HIDn + k0] : 0.f;
            float w1 = (k1 < HIDn) ? wt[(size_t)o * HIDn + k1] : 0.f;
            float w2 = (k2 < HIDn) ? wt[(size_t)o * HIDn + k2] : 0.f;
            float w3 = (k3 < HIDn) ? wt[(size_t)o * HIDn + k3] : 0.f;
            uint16_t h0, l0, h1, l1, h2, l2, h3, l3;
            bsplit(w0, h0, l0); bsplit(w1, h1, l1);
            bsplit(w2, h2, l2); bsplit(w3, h3, l3);
            BF[(kb * 8 + n8) * 32 + ln2] =
                make_uint4(pk2(h0, h1), pk2(h2, h3), pk2(l0, l1), pk2(l2, l3));
        }
        __syncthreads();
        // ---- GEMM: warp = 16 px x 64 out ----
        uint32_t xbase = (uint32_t)__cvta_generic_to_shared(Xh);
        int r = lane & 7, madd8 = (lane >> 3) & 1, gsel = lane >> 4;
        uint32_t abase = xbase + (warp * 16 + r + madd8 * 8) * 272 + gsel * 16;
        #pragma unroll
        for (int kb = 0; kb < 4; kb++) {
            if (kb >= nkb) break;
            uint32_t Ah0[4], Al0[4];
            uint32_t ah = abase + kb * 32;
            ldsm4(Ah0, ah);
            ldsm4(Al0, ah + 144);
            const uint4* bfk = BF + (size_t)kb * 8 * 32;
            #pragma unroll
            for (int n8 = 0; n8 < 8; n8++) {
                uint4 bv = bfk[n8 * 32 + lane];
                mma_bf16(acc[n8], Ah0, bv.x, bv.y);
                mma_bf16(acc[n8], Al0, bv.x, bv.y);
                mma_bf16(acc[n8], Ah0, bv.z, bv.w);
            }
        }
    }
    // epilogue: + resid (fp32 out, scattered)
    int gq = lane >> 2, oq = (lane & 3) * 2;
    int pxa = warp * 16 + gq, pxb = pxa + 8;
    #pragma unroll
    for (int n8 = 0; n8 < 8; n8++) {
        #pragma unroll
        for (int q = 0; q < 2; q++) {
            int og = n8 * 8 + oq + q;
            size_t obase = ((size_t)b * 64 + og) * HW + p0;
            out[obase + pxa] = acc[n8][q]     + resid[obase + pxa];
            out[obase + pxb] = acc[n8][q + 2] + resid[obase + pxb];
        }
    }
}

// ---------------- depthwise 3x3 conv, fp16 I/O, 8 px/thread ----------------
__global__ void dwconv_kernel(const __half* __restrict__ in, const float* __restrict__ wt,
                              __half* __restrict__ out, int Ch)
{
    int c = blockIdx.y, b = blockIdx.z;
    int p = (blockIdx.x * 256 + threadIdx.x) << 3;
    int h = p >> 7, w0 = p & 127;
    const __half* ib = in + ((size_t)b * Ch + c) * HW;
    const float* wc = wt + c * 9;
    float acc[8] = {0.f,0.f,0.f,0.f,0.f,0.f,0.f,0.f};
    #pragma unroll
    for (int dy = -1; dy <= 1; dy++) {
        int hh = h + dy;
        if ((unsigned)hh > 127u) continue;
        const __half* row = ib + (hh << 7);
        uint4 mraw = *(const uint4*)(row + w0);
        const __half2* m2 = (const __half2*)&mraw;
        float r[10];
        r[0] = (w0 > 0)   ? __half2float(row[w0 - 1]) : 0.f;
        #pragma unroll
        for (int k = 0; k < 4; k++) {
            float2 f = __half22float2(m2[k]);
            r[1 + 2 * k] = f.x; r[2 + 2 * k] = f.y;
        }
        r[9] = (w0 < 120) ? __half2float(row[w0 + 8]) : 0.f;
        float wa = wc[(dy + 1) * 3 + 0], wb = wc[(dy + 1) * 3 + 1], wcc = wc[(dy + 1) * 3 + 2];
        #pragma unroll
        for (int j = 0; j < 8; j++)
            acc[j] += wa * r[j] + wb * r[j + 1] + wcc * r[j + 2];
    }
    __half2 o2[4];
    #pragma unroll
    for (int k = 0; k < 4; k++) o2[k] = __floats2half2_rn(acc[2 * k], acc[2 * k + 1]);
    *(uint4*)(out + ((size_t)b * Ch + c) * HW + p) = *(uint4*)o2;
}

// =================================================================
// RSA window attention (fp16 qkv in) + fused proj conv + inverse roll
// =================================================================
__global__ void __launch_bounds__(256, 3)
rsa_attn_kernel(const __half* __restrict__ qkv, const float* __restrict__ pw,
                float* __restrict__ out, const float* __restrict__ temp)
{
    extern __shared__ float sm[];
    float* A   = sm;
    float* B   = sm + 64 * WSTR;
    float* C   = sm + 2 * 64 * WSTR;
    float* Pw  = sm + 3 * 64 * WSTR;
    float* inv = Pw + 64 * WSTR;
    int blk = blockIdx.x;
    int b = blk >> 8, win = blk & 255;
    int wy = win >> 4, wx = win & 15;
    int tid = threadIdx.x;
    size_t qbase = (size_t)b * 192 * HW;

    for (int e = tid; e < 4096; e += 256) {
        int p = e & 63, c = e >> 6;
        int gp = (((wy << 3) + (p >> 3)) << 7) | ((wx << 3) + (p & 7));
        A[p * WSTR + c] = __half2float(qkv[qbase + c * HW + gp]);
        B[p * WSTR + c] = __half2float(qkv[qbase + (64 + c) * HW + gp]);
        Pw[(e & 63) * WSTR + (e >> 6)] = pw[e];
    }
    __syncthreads();
    if (tid < 64) {
        int p = tid;
        float nq = 0.f, nk = 0.f;
        #pragma unroll
        for (int c = 0; c < 64; c++) {
            float a = A[p * WSTR + c]; nq += a * a;
            float bb = B[p * WSTR + c]; nk += bb * bb;
        }
        inv[p] = 1.0f / (fmaxf(sqrtf(nq), 1e-12f) * fmaxf(sqrtf(nk), 1e-12f));
    }
    __syncthreads();
    for (int e4 = tid; e4 < 1024; e4 += 256) {
        int p = e4 >> 4, c4 = e4 & 15;
        float iv = inv[p];
        float4 v = ((float4*)B)[p * (WSTR / 4) + c4];
        v.x *= iv; v.y *= iv; v.z *= iv; v.w *= iv;
        ((float4*)B)[p * (WSTR / 4) + c4] = v;
    }
    __syncthreads();
    float tscale = temp[0];
    {   // GEMM1: attn
        int c0 = (tid >> 4) << 2, d0 = (tid & 15) << 2;
        float s[4][4] = {};
        #pragma unroll 4
        for (int p = 0; p < 64; p++) {
            float4 qv = *(const float4*)(A + p * WSTR + c0);
            float4 kv = *(const float4*)(B + p * WSTR + d0);
            float qr[4] = {qv.x, qv.y, qv.z, qv.w};
            float kr[4] = {kv.x, kv.y, kv.z, kv.w};
            #pragma unroll
            for (int i = 0; i < 4; i++)
                #pragma unroll
                for (int j = 0; j < 4; j++) s[i][j] += qr[i] * kr[j];
        }
        #pragma unroll
        for (int i = 0; i < 4; i++)
            *(float4*)(C + (c0 + i) * WSTR + d0) =
                make_float4(fmaxf(0.f, tscale * s[i][0]), fmaxf(0.f, tscale * s[i][1]),
                            fmaxf(0.f, tscale * s[i][2]), fmaxf(0.f, tscale * s[i][3]));
    }
    __syncthreads();
    for (int e = tid; e < 4096; e += 256) {
        int p = e & 63, c = e >> 6;
        int gp = (((wy << 3) + (p >> 3)) << 7) | ((wx << 3) + (p & 7));
        A[c * WSTR + p] = __half2float(qkv[qbase + (128 + c) * HW + gp]);
    }
    __syncthreads();
    {   // GEMM2: out[d][p]
        int p0 = (tid >> 4) << 2, d0 = (tid & 15) << 2;
        float s[4][4] = {};
        #pragma unroll 4
        for (int c = 0; c < 64; c++) {
            float4 vv = *(const float4*)(A + c * WSTR + p0);
            float4 av = *(const float4*)(C + c * WSTR + d0);
            float vr[4] = {vv.x, vv.y, vv.z, vv.w};
            float ar[4] = {av.x, av.y, av.z, av.w};
            #pragma unroll
            for (int i = 0; i < 4; i++)
                #pragma unroll
                for (int j = 0; j < 4; j++) s[i][j] += vr[i] * ar[j];
        }
        #pragma unroll
        for (int j = 0; j < 4; j++)
            *(float4*)(B + (d0 + j) * WSTR + p0) = make_float4(s[0][j], s[1][j], s[2][j], s[3][j]);
    }
    __syncthreads();
    {   // GEMM3: proj
        int o0 = (tid >> 4) << 2, p0 = (tid & 15) << 2;
        float s[4][4] = {};
        #pragma unroll 4
        for (int d = 0; d < 64; d++) {
            float4 wv = *(const float4*)(Pw + d * WSTR + o0);
            float4 bv = *(const float4*)(B + d * WSTR + p0);
            float wr[4] = {wv.x, wv.y, wv.z, wv.w};
            float br[4] = {bv.x, bv.y, bv.z, bv.w};
            #pragma unroll
            for (int i = 0; i < 4; i++)
                #pragma unroll
                for (int j = 0; j < 4; j++) s[i][j] += wr[i] * br[j];
        }
        #pragma unroll
        for (int i = 0; i < 4; i++)
            *(float4*)(C + (o0 + i) * WSTR + p0) = make_float4(s[i][0], s[i][1], s[i][2], s[i][3]);
    }
    __syncthreads();
    size_t obase = (size_t)b * 64 * HW;
    for (int e = tid; e < 4096; e += 256) {
        int p = e & 63, o = e >> 6;
        int gh = (((wy << 3) + (p >> 3)) + 4) & 127;
        int gw = (((wx << 3) + (p & 7)) + 4) & 127;
        out[obase + o * HW + (gh << 7) + gw] = C[o * WSTR + p];
    }
}

// ---------------- GSA: partial Gram sums (fp16 qkv in) ---------------------------
__global__ void gsa_attn_part(const __half* __restrict__ qkv, float* __restrict__ part)
{
    __shared__ float red[8][80];
    int bh = blockIdx.y;
    int b = bh >> 3, hd = bh & 7;
    int chunk = blockIdx.x;
    int tid = threadIdx.x;
    const __half* qb = qkv + ((size_t)b * 192 + hd * 8) * HW;
    const __half* kb = qkv + ((size_t)b * 192 + 64 + hd * 8) * HW;
    float dot[8][8] = {};
    float qn[8] = {}, kn[8] = {};
    int n0 = chunk * 2048;
    for (int n = n0 + tid; n < n0 + 2048; n += 256) {
        float qv[8], kv[8];
        #pragma unroll
        for (int i = 0; i < 8; i++) {
            qv[i] = __half2float(qb[i * HW + n]);
            kv[i] = __half2float(kb[i * HW + n]);
        }
        #pragma unroll
        for (int i = 0; i < 8; i++) { qn[i] += qv[i] * qv[i]; kn[i] += kv[i] * kv[i]; }
        #pragma unroll
        for (int i = 0; i < 8; i++)
            #pragma unroll
            for (int j = 0; j < 8; j++) dot[i][j] += qv[i] * kv[j];
    }
    int lane = tid & 31, w = tid >> 5;
    #pragma unroll
    for (int i = 0; i < 8; i++)
        #pragma unroll
        for (int j = 0; j < 8; j++) {
            float v = dot[i][j];
            #pragma unroll
            for (int off = 16; off; off >>= 1) v += __shfl_xor_sync(0xffffffffu, v, off);
            if (lane == 0) red[w][i * 8 + j] = v;
        }
    #pragma unroll
    for (int i = 0; i < 8; i++) {
        float v = qn[i];
        #pragma unroll
        for (int off = 16; off; off >>= 1) v += __shfl_xor_sync(0xffffffffu, v, off);
        if (lane == 0) red[w][64 + i] = v;
        float u = kn[i];
        #pragma unroll
        for (int off = 16; off; off >>= 1) u += __shfl_xor_sync(0xffffffffu, u, off);
        if (lane == 0) red[w][72 + i] = u;
    }
    __syncthreads();
    if (tid < 80) {
        float s = 0.f;
        #pragma unroll
        for (int w2 = 0; w2 < 8; w2++) s += red[w2][tid];
        part[((size_t)bh * 8 + chunk) * 80 + tid] = s;
    }
}

__global__ void gsa_attn_final(const float* __restrict__ part, float* __restrict__ attn,
                               const float* __restrict__ temp)
{
    __shared__ float fin[80];
    int bh = blockIdx.x, tid = threadIdx.x;
    if (tid < 80) {
        float s = 0.f;
        #pragma unroll
        for (int c = 0; c < 8; c++) s += part[((size_t)bh * 8 + c) * 80 + tid];
        fin[tid] = s;
    }
    __syncthreads();
    if (tid < 64) {
        int c = tid >> 3, d = tid & 7;
        float nq = fmaxf(sqrtf(fin[64 + c]), 1e-12f);
        float nk = fmaxf(sqrtf(fin[72 + d]), 1e-12f);
        attn[(size_t)bh * 64 + tid] = fmaxf(0.f, temp[0] * fin[tid] / (nq * nk));
    }
}

// ---------------- GSA: fold proj into attention matrix -------------------------
__global__ void gsa_makeM(const float* __restrict__ attn, const float* __restrict__ pw,
                          float* __restrict__ M)
{
    __shared__ float at[512];
    int b = blockIdx.x, tid = threadIdx.x;
    for (int e = tid; e < 512; e += 256) at[e] = attn[(size_t)b * 512 + e];
    __syncthreads();
    for (int t = 0; t < 16; t++) {
        int e = t * 256 + tid;
        int o = e >> 6, chp = e & 63;
        int hd = chp >> 3, d = chp & 7;
        float s = 0.f;
        #pragma unroll
        for (int c = 0; c < 8; c++)
            s += pw[(size_t)o * 64 + c * 8 + hd] * at[hd * 64 + c * 8 + d];
        M[(size_t)b * 4096 + e] = s;
    }
}

// ---------------- GSA: out = M @ v (fp16 v in, proj included) --------------------
__global__ void gsa_mv_kernel(const __half* __restrict__ qkv, const float* __restrict__ M,
                              float* __restrict__ out)
{
    __shared__ float Ms[4096];
    int b = blockIdx.y, tid = threadIdx.x;
    for (int e = tid; e < 4096; e += 256) Ms[e] = M[(size_t)b * 4096 + e];
    __syncthreads();
    int n = blockIdx.x * 256 + tid;
    const __half* vb = qkv + ((size_t)b * 192 + 128) * HW + n;
    float* ob = out + (size_t)b * 64 * HW + n;
    float vv[64];
    #pragma unroll
    for (int c = 0; c < 64; c++) vv[c] = __half2float(vb[(size_t)c * HW]);
    #pragma unroll
    for (int og = 0; og < 8; og++) {
        float acc[8] = {0.f,0.f,0.f,0.f,0.f,0.f,0.f,0.f};
        #pragma unroll
        for (int c = 0; c < 64; c++) {
            float v = vv[c];
            #pragma unroll
            for (int j = 0; j < 8; j++) acc[j] += Ms[(og * 8 + j) * 64 + c] * v;
        }
        #pragma unroll
        for (int j = 0; j < 8; j++) ob[(size_t)(og * 8 + j) * HW] = acc[j];
    }
}

// ---------------- launch ---------------------------------------------------------
extern "C" void kernel_launch(void* const* d_in, const int* in_sizes, int n_in,
                              void* d_out, int out_size)
{
    const float* x         = (const float*)d_in[0];
    const float* ln_s0_w   = (const float*)d_in[1];
    const float* ln_s0_b   = (const float*)d_in[2];
    const float* ln_s2_w   = (const float*)d_in[3];
    const float* ln_s2_b   = (const float*)d_in[4];
    const float* rsa_qkv_w = (const float*)d_in[5];
    const float* rsa_dw_w  = (const float*)d_in[6];
    const float* rsa_proj_w= (const float*)d_in[7];
    const float* rsa_temp  = (const float*)d_in[8];
    const float* ffs_in_w  = (const float*)d_in[9];
    const float* ffs_dw_w  = (const float*)d_in[10];
    const float* ffs_out_w = (const float*)d_in[11];
    const float* ln_c0_w   = (const float*)d_in[12];
    const float* ln_c0_b   = (const float*)d_in[13];
    const float* ln_c2_w   = (const float*)d_in[14];
    const float* ln_c2_b   = (const float*)d_in[15];
    const float* gsa_qkv_w = (const float*)d_in[16];
    const float* gsa_dw_w  = (const float*)d_in[17];
    const float* gsa_proj_w= (const float*)d_in[18];
    const float* gsa_temp  = (const float*)d_in[19];
    const float* ffc_in_w  = (const float*)d_in[20];
    const float* ffc_dw_w  = (const float*)d_in[21];
    const float* ffc_out_w = (const float*)d_in[22];
    float* outp = (float*)d_out;

    float *bufR, *bufX, *bufG, *attnb, *partb, *Mb;
    __half *big1, *big2;
    cudaGetSymbolAddress((void**)&bufR,  g_bufR);
    cudaGetSymbolAddress((void**)&bufX,  g_bufX);
    cudaGetSymbolAddress((void**)&bufG,  g_bufG);
    cudaGetSymbolAddress((void**)&big1,  g_big1);
    cudaGetSymbolAddress((void**)&big2,  g_big2);
    cudaGetSymbolAddress((void**)&attnb, g_attn);
    cudaGetSymbolAddress((void**)&partb, g_part);
    cudaGetSymbolAddress((void**)&Mb,    g_M);

    // convtc: X(17408) + BFx2(8192) + mu/rs(512) + sg/sb(256) = 26368 floats = 105472 B
    const int ctc_smem = (256 * XSTR + 8192 + 256 + 256 + 128 + 128) * (int)sizeof(float);
    const int cg_smem  = (128 * XSTR + 4096) * (int)sizeof(float);   // 51200
    const int rsa_smem = (4 * 64 * WSTR + 64) * (int)sizeof(float);
    cudaFuncSetAttribute(convtc_kernel, cudaFuncAttributeMaxDynamicSharedMemorySize, ctc_smem);
    cudaFuncSetAttribute(convgate_kernel, cudaFuncAttributeMaxDynamicSharedMemorySize, cg_smem);
    cudaFuncSetAttribute(rsa_attn_kernel, cudaFuncAttributeMaxDynamicSharedMemorySize, rsa_smem);

    // ---- stage 1: RSA + spatial FFN ----
    convtc_kernel<<<dim3(64, 1, Bn), 256, ctc_smem>>>(x, nullptr, ln_s0_w, ln_s0_b, rsa_qkv_w, big1, 192, 4);
    dwconv_kernel<<<dim3(8, 192, Bn), 256>>>(big1, rsa_dw_w, big2, 192);
    rsa_attn_kernel<<<Bn * 256, 256, rsa_smem>>>(big2, rsa_proj_w, bufR, rsa_temp);
    convtc_kernel<<<dim3(64, 1, Bn), 256, ctc_smem>>>(bufR, x, ln_s2_w, ln_s2_b, ffs_in_w, big1, 340, 0);
    dwconv_kernel<<<dim3(8, 340, Bn), 256>>>(big1, ffs_dw_w, big2, 340);
    convgate_kernel<<<dim3(128, 1, Bn), 256, cg_smem>>>(big2, ffs_out_w, bufX, bufR);

    // ---- stage 2: GSA + channel FFN ----
    convtc_kernel<<<dim3(64, 1, Bn), 256, ctc_smem>>>(bufX, nullptr, ln_c0_w, ln_c0_b, gsa_qkv_w, big1, 192, 0);
    dwconv_kernel<<<dim3(8, 192, Bn), 256>>>(big1, gsa_dw_w, big2, 192);
    gsa_attn_part<<<dim3(8, 64), 256>>>(big2, partb);
    gsa_attn_final<<<64, 128>>>(partb, attnb, gsa_temp);
    gsa_makeM<<<Bn, 256>>>(attnb, gsa_proj_w, Mb);
    gsa_mv_kernel<<<dim3(64, Bn), 256>>>(big2, Mb, bufG);
    convtc_kernel<<<dim3(64, 1, Bn), 256, ctc_smem>>>(bufG, bufX, ln_c2_w, ln_c2_b, ffc_in_w, big1, 340, 0);
    dwconv_kernel<<<dim3(8, 340, Bn), 256>>>(big1, ffc_dw_w, big2, 340);
    convgate_kernel<<<dim3(128, 1, Bn), 256, cg_smem>>>(big2, ffc_out_w, outp, bufG);
}

// round 15
// speedup vs baseline: 1.1774x; 1.0264x over previous
#include <cuda_runtime.h>
#include <cuda_fp16.h>
#include <math.h>
#include <stdint.h>

#define HW    16384
#define Bn    8
#define HIDn  170
#define XSTR  68      // floats per X row = 272B = 17 x 16B granules (conflict-free)
#define WSTR  68

// ---------------- scratch (static device memory) ----------------
__device__ float  g_bufR[Bn * 64 * HW];
__device__ float  g_bufX[Bn * 64 * HW];
__device__ float  g_bufG[Bn * 64 * HW];
__device__ __half g_big1[Bn * 340 * HW];
__device__ __half g_big2[Bn * 340 * HW];
__device__ float  g_attn[Bn * 8 * 64];
__device__ float  g_part[64 * 8 * 80];
__device__ float  g_M[Bn * 64 * 64];

__device__ __forceinline__ float gelu_f(float x) {
    return 0.5f * x * (1.0f + erff(x * 0.70710678118654752f));
}
__device__ __forceinline__ uint16_t f16b(float x) {
    uint16_t r; asm("cvt.rn.f16.f32 %0, %1;" : "=h"(r) : "f"(x)); return r;
}
__device__ __forceinline__ uint32_t pk2(uint16_t lo, uint16_t hi) {
    return (uint32_t)lo | ((uint32_t)hi << 16);
}
// 2-term fp16 split: v = h + l with h,l fp16 (x error ~2^-23)
__device__ __forceinline__ void fsplit(float v, uint16_t& h, uint16_t& l) {
    h = f16b(v);
    float hf; asm("cvt.f32.f16 %0, %1;" : "=f"(hf) : "h"(h));
    l = f16b(v - hf);
}
__device__ __forceinline__ void ldsm4(uint32_t* a, uint32_t addr) {
    asm volatile("ldmatrix.sync.aligned.m8n8.x4.shared.b16 {%0,%1,%2,%3}, [%4];"
        : "=r"(a[0]), "=r"(a[1]), "=r"(a[2]), "=r"(a[3]) : "r"(addr));
}
__device__ __forceinline__ void mma_f16(float* d, const uint32_t* a, uint32_t b0, uint32_t b1) {
    asm volatile("mma.sync.aligned.m16n8k16.row.col.f32.f16.f16.f32 "
        "{%0,%1,%2,%3}, {%4,%5,%6,%7}, {%8,%9}, {%0,%1,%2,%3};"
        : "+f"(d[0]), "+f"(d[1]), "+f"(d[2]), "+f"(d[3])
        : "r"(a[0]), "r"(a[1]), "r"(a[2]), "r"(a[3]), "r"(b0), "r"(b1));
}

// =================================================================
// LN-fused tensor-core conv1x1 (Cin=64, fp32 in), 2-term fp16
// (x hi+lo fp16, w single fp16), fp16 output. 256-px tiles,
// 2 CTAs/SM, warp = 32px x 64out. Double-buffered W staging.
// =================================================================
__global__ void __launch_bounds__(256, 2)
convtc_kernel(const float* __restrict__ in, const float* __restrict__ addp,
              const float* __restrict__ lnw, const float* __restrict__ lnb,
              const float* __restrict__ wt, __half* __restrict__ out,
              int Cout, int shift)
{
    extern __shared__ float sm[];
    float* Xh   = sm;                         // 256 x 272B rows (17408 floats)
    uint2* BF   = (uint2*)(sm + 256 * XSTR);  // 2 x [4kb][8n8][32] uint2 = 16KB
    float* mu_s = sm + 256 * XSTR + 4096;     // [256]
    float* rs_s = mu_s + 256;                 // [256]
    float* sg_s = rs_s + 256;                 // [128] (2 slots of 64)
    float* sb_s = sg_s + 128;                 // [128]

    int b = blockIdx.z, p0 = blockIdx.x * 256;
    int tid = threadIdx.x, warp = tid >> 5, lane = tid & 31;
    const float* inb = in + (size_t)b * 64 * HW;
    const float* adb = addp ? addp + (size_t)b * 64 * HW : nullptr;

    int p = p0 + tid, ip = p;
    if (shift) {
        int hh = ((p >> 7) + shift) & 127, ww = ((p & 127) + shift) & 127;
        ip = (hh << 7) | ww;
    }
    // ---- stage X once (fp16 hi/lo) + LN stats ----
    float s_sum = 0.f, s_sq = 0.f;
    char* xrow = (char*)Xh + tid * 272;
    #pragma unroll
    for (int j8 = 0; j8 < 8; j8++) {
        uint16_t hb[8], lb[8];
        #pragma unroll
        for (int jj = 0; jj < 8; jj++) {
            int c = j8 * 8 + jj;
            float v = inb[(size_t)c * HW + ip];
            if (adb) v += adb[(size_t)c * HW + ip];
            s_sum += v; s_sq += v * v;
            fsplit(v, hb[jj], lb[jj]);
        }
        *(uint4*)(xrow + j8 * 16) =
            make_uint4(pk2(hb[0], hb[1]), pk2(hb[2], hb[3]), pk2(hb[4], hb[5]), pk2(hb[6], hb[7]));
        *(uint4*)(xrow + 144 + j8 * 16) =
            make_uint4(pk2(lb[0], lb[1]), pk2(lb[2], lb[3]), pk2(lb[4], lb[5]), pk2(lb[6], lb[7]));
    }
    {
        float m = s_sum * 0.015625f;
        float var = s_sq * 0.015625f - m * m;
        mu_s[tid] = m;
        rs_s[tid] = rsqrtf(fmaxf(var, 0.f) + 1e-5f);
    }

    int ntile = (Cout + 63) >> 6;

    // stage tile `tt` weights (single fp16) into BF slot `sl`
    #define STAGE_W(tt, sl)                                                              \
    {                                                                                    \
        int o0s = (tt) << 6;                                                             \
        uint2* bfs = BF + (size_t)(sl) * 1024;                                           \
        _Pragma("unroll")                                                                \
        for (int i = 0; i < 4; i++) {                                                    \
            int e = i * 256 + tid;                                                       \
            int kb = e >> 8, rem = e & 255;                                              \
            int n8 = rem >> 5, ln2 = rem & 31;                                           \
            int g = ln2 >> 2, t2 = ln2 & 3;                                              \
            int og = o0s + n8 * 8 + g;                                                   \
            int kbase = kb * 16;                                                         \
            float w0 = 0.f, w1 = 0.f, w2 = 0.f, w3 = 0.f;                                \
            if (og < Cout) {                                                             \
                const float* wr = wt + (size_t)og * 64 + kbase;                          \
                w0 = wr[2 * t2]     * lnw[kbase + 2 * t2];                               \
                w1 = wr[2 * t2 + 1] * lnw[kbase + 2 * t2 + 1];                           \
                w2 = wr[2 * t2 + 8] * lnw[kbase + 2 * t2 + 8];                           \
                w3 = wr[2 * t2 + 9] * lnw[kbase + 2 * t2 + 9];                           \
            }                                                                            \
            bfs[(kb * 8 + n8) * 32 + ln2] =                                              \
                make_uint2(pk2(f16b(w0), f16b(w1)), pk2(f16b(w2), f16b(w3)));            \
        }                                                                                \
        if (tid < 64) {                                                                  \
            float sg = 0.f, sb2 = 0.f;                                                   \
            int og = o0s + tid;                                                          \
            if (og < Cout) {                                                             \
                const float* wr = wt + (size_t)og * 64;                                  \
                _Pragma("unroll 8")                                                      \
                for (int k = 0; k < 64; k++) { sg += wr[k] * lnw[k]; sb2 += wr[k] * lnb[k]; } \
            }                                                                            \
            sg_s[(sl) * 64 + tid] = sg; sb_s[(sl) * 64 + tid] = sb2;                     \
        }                                                                                \
    }

    STAGE_W(0, 0);
    __syncthreads();

    for (int t = 0; t < ntile; t++) {
        int slot = t & 1;
        int o0 = t << 6;
        // ---- tensor GEMM: 4 kb16 steps, 2-term fp16 ----
        float accD[2][8][4] = {};
        uint32_t xbase = (uint32_t)__cvta_generic_to_shared(Xh);
        int r = lane & 7, madd8 = (lane >> 3) & 1, gsel = lane >> 4;
        uint32_t abase = xbase + (warp * 32 + r + madd8 * 8) * 272 + gsel * 16;
        const uint2* bfb = BF + (size_t)slot * 1024;
        #pragma unroll
        for (int kb = 0; kb < 4; kb++) {
            uint32_t Ah0[4], Ah1[4], Al0[4], Al1[4];
            uint32_t ah = abase + kb * 32;
            ldsm4(Ah0, ah);
            ldsm4(Ah1, ah + 16 * 272);
            ldsm4(Al0, ah + 144);
            ldsm4(Al1, ah + 144 + 16 * 272);
            const uint2* bfk = bfb + (size_t)kb * 8 * 32;
            #pragma unroll
            for (int n8 = 0; n8 < 8; n8++) {
                uint2 bv = bfk[n8 * 32 + lane];
                mma_f16(accD[0][n8], Ah0, bv.x, bv.y);
                mma_f16(accD[0][n8], Al0, bv.x, bv.y);
                mma_f16(accD[1][n8], Ah1, bv.x, bv.y);
                mma_f16(accD[1][n8], Al1, bv.x, bv.y);
            }
        }
        // ---- stage NEXT tile's weights (overlaps epilogue) ----
        if (t + 1 < ntile) STAGE_W(t + 1, 1 - slot);
        // ---- epilogue (LN transform, scattered fp16 stores) ----
        int gq = lane >> 2, oq = (lane & 3) * 2;
        const float* sgp = sg_s + slot * 64;
        const float* sbp = sb_s + slot * 64;
        #pragma unroll
        for (int tt = 0; tt < 2; tt++) {
            int pxa = warp * 32 + tt * 16 + gq;
            int pxb = pxa + 8;
            float mua = mu_s[pxa], rsa_ = rs_s[pxa];
            float mub = mu_s[pxb], rsb = rs_s[pxb];
            #pragma unroll
            for (int n8 = 0; n8 < 8; n8++) {
                #pragma unroll
                for (int q = 0; q < 2; q++) {
                    int ol = n8 * 8 + oq + q;
                    int og = o0 + ol;
                    if (og < Cout) {
                        float sg = sgp[ol], sb = sbp[ol];
                        float v0 = rsa_ * (accD[tt][n8][q]     - mua * sg) + sb;
                        float v1 = rsb  * (accD[tt][n8][q + 2] - mub * sg) + sb;
                        size_t obase = ((size_t)b * Cout + og) * HW + p0;
                        out[obase + pxa] = __float2half(v0);
                        out[obase + pxb] = __float2half(v1);
                    }
                }
            }
        }
        __syncthreads();
    }
    #undef STAGE_W
}

// =================================================================
// gated tensor-core conv (fp16 in, Cin=170 phys 340), 2-term fp16,
// fp32 out + resid, scattered epilogue.
// =================================================================
__global__ void __launch_bounds__(256, 3)
convgate_kernel(const __half* __restrict__ in, const float* __restrict__ wt,
                float* __restrict__ out, const float* __restrict__ resid)
{
    extern __shared__ float sm[];
    float* Xh = sm;                          // 128 x 272B rows
    uint2* BF = (uint2*)(sm + 128 * XSTR);   // [4kb][8n8][32] uint2 = 8KB

    int b = blockIdx.z, p0 = blockIdx.x * 128;
    int tid = threadIdx.x, warp = tid >> 5, lane = tid & 31;
    int px = tid & 127, half = tid >> 7;
    int ip = p0 + px;
    const __half* inb = in + (size_t)b * 340 * HW;

    float acc[8][4] = {};
    const int kbs16[3] = {4, 4, 3};
    for (int ch = 0; ch < 3; ch++) {
        if (ch) __syncthreads();
        int c0 = ch * 64;
        int nkb = kbs16[ch];
        // ---- stage X: 2 threads/px, 32 channels each (fp16 hi/lo) ----
        char* xrow = (char*)Xh + px * 272;
        #pragma unroll
        for (int j8 = 0; j8 < 4; j8++) {
            uint16_t hb[8], lb[8];
            #pragma unroll
            for (int jj = 0; jj < 8; jj++) {
                int c = c0 + half * 32 + j8 * 8 + jj;
                float v = 0.f;
                if (c < HIDn) {
                    float a = __half2float(inb[(size_t)c * HW + ip]);
                    float g = __half2float(inb[(size_t)(c + HIDn) * HW + ip]);
                    v = gelu_f(a) * g;
                }
                fsplit(v, hb[jj], lb[jj]);
            }
            *(uint4*)(xrow + half * 64 + j8 * 16) =
                make_uint4(pk2(hb[0], hb[1]), pk2(hb[2], hb[3]), pk2(hb[4], hb[5]), pk2(hb[6], hb[7]));
            *(uint4*)(xrow + 144 + half * 64 + j8 * 16) =
                make_uint4(pk2(lb[0], lb[1]), pk2(lb[2], lb[3]), pk2(lb[4], lb[5]), pk2(lb[6], lb[7]));
        }
        // ---- stage BF (single fp16 w) ----
        int tot = nkb * 256;
        for (int e = tid; e < tot; e += 256) {
            int kb = e >> 8, rem = e & 255;
            int n8 = rem >> 5, ln2 = rem & 31;
            int g = ln2 >> 2, t2 = ln2 & 3;
            int o = n8 * 8 + g;
            int kbase = c0 + kb * 16;
            int k0 = kbase + 2 * t2, k1 = k0 + 1, k2 = kbase + 2 * t2 + 8, k3 = k2 + 1;
            float w0 = (k0 < HIDn) ? wt[(size_t)o * HIDn + k0] : 0.f;
            float w1 = (k1 < HIDn) ? wt[(size_t)o * HIDn + k1] : 0.f;
            float w2 = (k2 < HIDn) ? wt[(size_t)o * HIDn + k2] : 0.f;
            float w3 = (k3 < HIDn) ? wt[(size_t)o * HIDn + k3] : 0.f;
            BF[(kb * 8 + n8) * 32 + ln2] =
                make_uint2(pk2(f16b(w0), f16b(w1)), pk2(f16b(w2), f16b(w3)));
        }
        __syncthreads();
        // ---- GEMM: warp = 16 px x 64 out, 2-term fp16 ----
        uint32_t xbase = (uint32_t)__cvta_generic_to_shared(Xh);
        int r = lane & 7, madd8 = (lane >> 3) & 1, gsel = lane >> 4;
        uint32_t abase = xbase + (warp * 16 + r + madd8 * 8) * 272 + gsel * 16;
        #pragma unroll
        for (int kb = 0; kb < 4; kb++) {
            if (kb >= nkb) break;
            uint32_t Ah0[4], Al0[4];
            uint32_t ah = abase + kb * 32;
            ldsm4(Ah0, ah);
            ldsm4(Al0, ah + 144);
            const uint2* bfk = BF + (size_t)kb * 8 * 32;
            #pragma unroll
            for (int n8 = 0; n8 < 8; n8++) {
                uint2 bv = bfk[n8 * 32 + lane];
                mma_f16(acc[n8], Ah0, bv.x, bv.y);
                mma_f16(acc[n8], Al0, bv.x, bv.y);
            }
        }
    }
    // epilogue: + resid (fp32 out, scattered)
    int gq = lane >> 2, oq = (lane & 3) * 2;
    int pxa = warp * 16 + gq, pxb = pxa + 8;
    #pragma unroll
    for (int n8 = 0; n8 < 8; n8++) {
        #pragma unroll
        for (int q = 0; q < 2; q++) {
            int og = n8 * 8 + oq + q;
            size_t obase = ((size_t)b * 64 + og) * HW + p0;
            out[obase + pxa] = acc[n8][q]     + resid[obase + pxa];
            out[obase + pxb] = acc[n8][q + 2] + resid[obase + pxb];
        }
    }
}

// ---------------- depthwise 3x3 conv, fp16 I/O, 8 px/thread ----------------
__global__ void dwconv_kernel(const __half* __restrict__ in, const float* __restrict__ wt,
                              __half* __restrict__ out, int Ch)
{
    int c = blockIdx.y, b = blockIdx.z;
    int p = (blockIdx.x * 256 + threadIdx.x) << 3;
    int h = p >> 7, w0 = p & 127;
    const __half* ib = in + ((size_t)b * Ch + c) * HW;
    const float* wc = wt + c * 9;
    float acc[8] = {0.f,0.f,0.f,0.f,0.f,0.f,0.f,0.f};
    #pragma unroll
    for (int dy = -1; dy <= 1; dy++) {
        int hh = h + dy;
        if ((unsigned)hh > 127u) continue;
        const __half* row = ib + (hh << 7);
        uint4 mraw = *(const uint4*)(row + w0);
        const __half2* m2 = (const __half2*)&mraw;
        float r[10];
        r[0] = (w0 > 0)   ? __half2float(row[w0 - 1]) : 0.f;
        #pragma unroll
        for (int k = 0; k < 4; k++) {
            float2 f = __half22float2(m2[k]);
            r[1 + 2 * k] = f.x; r[2 + 2 * k] = f.y;
        }
        r[9] = (w0 < 120) ? __half2float(row[w0 + 8]) : 0.f;
        float wa = wc[(dy + 1) * 3 + 0], wb = wc[(dy + 1) * 3 + 1], wcc = wc[(dy + 1) * 3 + 2];
        #pragma unroll
        for (int j = 0; j < 8; j++)
            acc[j] += wa * r[j] + wb * r[j + 1] + wcc * r[j + 2];
    }
    __half2 o2[4];
    #pragma unroll
    for (int k = 0; k < 4; k++) o2[k] = __floats2half2_rn(acc[2 * k], acc[2 * k + 1]);
    *(uint4*)(out + ((size_t)b * Ch + c) * HW + p) = *(uint4*)o2;
}

// =================================================================
// RSA window attention (fp16 qkv in) + fused proj conv + inverse roll
// =================================================================
__global__ void __launch_bounds__(256, 3)
rsa_attn_kernel(const __half* __restrict__ qkv, const float* __restrict__ pw,
                float* __restrict__ out, const float* __restrict__ temp)
{
    extern __shared__ float sm[];
    float* A   = sm;
    float* B   = sm + 64 * WSTR;
    float* C   = sm + 2 * 64 * WSTR;
    float* Pw  = sm + 3 * 64 * WSTR;
    float* inv = Pw + 64 * WSTR;
    int blk = blockIdx.x;
    int b = blk >> 8, win = blk & 255;
    int wy = win >> 4, wx = win & 15;
    int tid = threadIdx.x;
    size_t qbase = (size_t)b * 192 * HW;

    for (int e = tid; e < 4096; e += 256) {
        int p = e & 63, c = e >> 6;
        int gp = (((wy << 3) + (p >> 3)) << 7) | ((wx << 3) + (p & 7));
        A[p * WSTR + c] = __half2float(qkv[qbase + c * HW + gp]);
        B[p * WSTR + c] = __half2float(qkv[qbase + (64 + c) * HW + gp]);
        Pw[(e & 63) * WSTR + (e >> 6)] = pw[e];
    }
    __syncthreads();
    if (tid < 64) {
        int p = tid;
        float nq = 0.f, nk = 0.f;
        #pragma unroll
        for (int c = 0; c < 64; c++) {
            float a = A[p * WSTR + c]; nq += a * a;
            float bb = B[p * WSTR + c]; nk += bb * bb;
        }
        inv[p] = 1.0f / (fmaxf(sqrtf(nq), 1e-12f) * fmaxf(sqrtf(nk), 1e-12f));
    }
    __syncthreads();
    for (int e4 = tid; e4 < 1024; e4 += 256) {
        int p = e4 >> 4, c4 = e4 & 15;
        float iv = inv[p];
        float4 v = ((float4*)B)[p * (WSTR / 4) + c4];
        v.x *= iv; v.y *= iv; v.z *= iv; v.w *= iv;
        ((float4*)B)[p * (WSTR / 4) + c4] = v;
    }
    __syncthreads();
    float tscale = temp[0];
    {
        int c0 = (tid >> 4) << 2, d0 = (tid & 15) << 2;
        float s[4][4] = {};
        #pragma unroll 4
        for (int p = 0; p < 64; p++) {
            float4 qv = *(const float4*)(A + p * WSTR + c0);
            float4 kv = *(const float4*)(B + p * WSTR + d0);
            float qr[4] = {qv.x, qv.y, qv.z, qv.w};
            float kr[4] = {kv.x, kv.y, kv.z, kv.w};
            #pragma unroll
            for (int i = 0; i < 4; i++)
                #pragma unroll
                for (int j = 0; j < 4; j++) s[i][j] += qr[i] * kr[j];
        }
        #pragma unroll
        for (int i = 0; i < 4; i++)
            *(float4*)(C + (c0 + i) * WSTR + d0) =
                make_float4(fmaxf(0.f, tscale * s[i][0]), fmaxf(0.f, tscale * s[i][1]),
                            fmaxf(0.f, tscale * s[i][2]), fmaxf(0.f, tscale * s[i][3]));
    }
    __syncthreads();
    for (int e = tid; e < 4096; e += 256) {
        int p = e & 63, c = e >> 6;
        int gp = (((wy << 3) + (p >> 3)) << 7) | ((wx << 3) + (p & 7));
        A[c * WSTR + p] = __half2float(qkv[qbase + (128 + c) * HW + gp]);
    }
    __syncthreads();
    {
        int p0 = (tid >> 4) << 2, d0 = (tid & 15) << 2;
        float s[4][4] = {};
        #pragma unroll 4
        for (int c = 0; c < 64; c++) {
            float4 vv = *(const float4*)(A + c * WSTR + p0);
            float4 av = *(const float4*)(C + c * WSTR + d0);
            float vr[4] = {vv.x, vv.y, vv.z, vv.w};
            float ar[4] = {av.x, av.y, av.z, av.w};
            #pragma unroll
            for (int i = 0; i < 4; i++)
                #pragma unroll
                for (int j = 0; j < 4; j++) s[i][j] += vr[i] * ar[j];
        }
        #pragma unroll
        for (int j = 0; j < 4; j++)
            *(float4*)(B + (d0 + j) * WSTR + p0) = make_float4(s[0][j], s[1][j], s[2][j], s[3][j]);
    }
    __syncthreads();
    {
        int o0 = (tid >> 4) << 2, p0 = (tid & 15) << 2;
        float s[4][4] = {};
        #pragma unroll 4
        for (int d = 0; d < 64; d++) {
            float4 wv = *(const float4*)(Pw + d * WSTR + o0);
            float4 bv = *(const float4*)(B + d * WSTR + p0);
            float wr[4] = {wv.x, wv.y, wv.z, wv.w};
            float br[4] = {bv.x, bv.y, bv.z, bv.w};
            #pragma unroll
            for (int i = 0; i < 4; i++)
                #pragma unroll
                for (int j = 0; j < 4; j++) s[i][j] += wr[i] * br[j];
        }
        #pragma unroll
        for (int i = 0; i < 4; i++)
            *(float4*)(C + (o0 + i) * WSTR + p0) = make_float4(s[i][0], s[i][1], s[i][2], s[i][3]);
    }
    __syncthreads();
    size_t obase = (size_t)b * 64 * HW;
    for (int e = tid; e < 4096; e += 256) {
        int p = e & 63, o = e >> 6;
        int gh = (((wy << 3) + (p >> 3)) + 4) & 127;
        int gw = (((wx << 3) + (p & 7)) + 4) & 127;
        out[obase + o * HW + (gh << 7) + gw] = C[o * WSTR + p];
    }
}

// ---------------- GSA: partial Gram sums (fp16 qkv in) ---------------------------
__global__ void gsa_attn_part(const __half* __restrict__ qkv, float* __restrict__ part)
{
    __shared__ float red[8][80];
    int bh = blockIdx.y;
    int b = bh >> 3, hd = bh & 7;
    int chunk = blockIdx.x;
    int tid = threadIdx.x;
    const __half* qb = qkv + ((size_t)b * 192 + hd * 8) * HW;
    const __half* kb = qkv + ((size_t)b * 192 + 64 + hd * 8) * HW;
    float dot[8][8] = {};
    float qn[8] = {}, kn[8] = {};
    int n0 = chunk * 2048;
    for (int n = n0 + tid; n < n0 + 2048; n += 256) {
        float qv[8], kv[8];
        #pragma unroll
        for (int i = 0; i < 8; i++) {
            qv[i] = __half2float(qb[i * HW + n]);
            kv[i] = __half2float(kb[i * HW + n]);
        }
        #pragma unroll
        for (int i = 0; i < 8; i++) { qn[i] += qv[i] * qv[i]; kn[i] += kv[i] * kv[i]; }
        #pragma unroll
        for (int i = 0; i < 8; i++)
            #pragma unroll
            for (int j = 0; j < 8; j++) dot[i][j] += qv[i] * kv[j];
    }
    int lane = tid & 31, w = tid >> 5;
    #pragma unroll
    for (int i = 0; i < 8; i++)
        #pragma unroll
        for (int j = 0; j < 8; j++) {
            float v = dot[i][j];
            #pragma unroll
            for (int off = 16; off; off >>= 1) v += __shfl_xor_sync(0xffffffffu, v, off);
            if (lane == 0) red[w][i * 8 + j] = v;
        }
    #pragma unroll
    for (int i = 0; i < 8; i++) {
        float v = qn[i];
        #pragma unroll
        for (int off = 16; off; off >>= 1) v += __shfl_xor_sync(0xffffffffu, v, off);
        if (lane == 0) red[w][64 + i] = v;
        float u = kn[i];
        #pragma unroll
        for (int off = 16; off; off >>= 1) u += __shfl_xor_sync(0xffffffffu, u, off);
        if (lane == 0) red[w][72 + i] = u;
    }
    __syncthreads();
    if (tid < 80) {
        float s = 0.f;
        #pragma unroll
        for (int w2 = 0; w2 < 8; w2++) s += red[w2][tid];
        part[((size_t)bh * 8 + chunk) * 80 + tid] = s;
    }
}

__global__ void gsa_attn_final(const float* __restrict__ part, float* __restrict__ attn,
                               const float* __restrict__ temp)
{
    __shared__ float fin[80];
    int bh = blockIdx.x, tid = threadIdx.x;
    if (tid < 80) {
        float s = 0.f;
        #pragma unroll
        for (int c = 0; c < 8; c++) s += part[((size_t)bh * 8 + c) * 80 + tid];
        fin[tid] = s;
    }
    __syncthreads();
    if (tid < 64) {
        int c = tid >> 3, d = tid & 7;
        float nq = fmaxf(sqrtf(fin[64 + c]), 1e-12f);
        float nk = fmaxf(sqrtf(fin[72 + d]), 1e-12f);
        attn[(size_t)bh * 64 + tid] = fmaxf(0.f, temp[0] * fin[tid] / (nq * nk));
    }
}

// ---------------- GSA: fold proj into attention matrix -------------------------
__global__ void gsa_makeM(const float* __restrict__ attn, const float* __restrict__ pw,
                          float* __restrict__ M)
{
    __shared__ float at[512];
    int b = blockIdx.x, tid = threadIdx.x;
    for (int e = tid; e < 512; e += 256) at[e] = attn[(size_t)b * 512 + e];
    __syncthreads();
    for (int t = 0; t < 16; t++) {
        int e = t * 256 + tid;
        int o = e >> 6, chp = e & 63;
        int hd = chp >> 3, d = chp & 7;
        float s = 0.f;
        #pragma unroll
        for (int c = 0; c < 8; c++)
            s += pw[(size_t)o * 64 + c * 8 + hd] * at[hd * 64 + c * 8 + d];
        M[(size_t)b * 4096 + e] = s;
    }
}

// ---------------- GSA: out = M @ v (fp16 v in, proj included) --------------------
__global__ void gsa_mv_kernel(const __half* __restrict__ qkv, const float* __restrict__ M,
                              float* __restrict__ out)
{
    __shared__ float Ms[4096];
    int b = blockIdx.y, tid = threadIdx.x;
    for (int e = tid; e < 4096; e += 256) Ms[e] = M[(size_t)b * 4096 + e];
    __syncthreads();
    int n = blockIdx.x * 256 + tid;
    const __half* vb = qkv + ((size_t)b * 192 + 128) * HW + n;
    float* ob = out + (size_t)b * 64 * HW + n;
    float vv[64];
    #pragma unroll
    for (int c = 0; c < 64; c++) vv[c] = __half2float(vb[(size_t)c * HW]);
    #pragma unroll
    for (int og = 0; og < 8; og++) {
        float acc[8] = {0.f,0.f,0.f,0.f,0.f,0.f,0.f,0.f};
        #pragma unroll
        for (int c = 0; c < 64; c++) {
            float v = vv[c];
            #pragma unroll
            for (int j = 0; j < 8; j++) acc[j] += Ms[(og * 8 + j) * 64 + c] * v;
        }
        #pragma unroll
        for (int j = 0; j < 8; j++) ob[(size_t)(og * 8 + j) * HW] = acc[j];
    }
}

// ---------------- launch ---------------------------------------------------------
extern "C" void kernel_launch(void* const* d_in, const int* in_sizes, int n_in,
                              void* d_out, int out_size)
{
    const float* x         = (const float*)d_in[0];
    const float* ln_s0_w   = (const float*)d_in[1];
    const float* ln_s0_b   = (const float*)d_in[2];
    const float* ln_s2_w   = (const float*)d_in[3];
    const float* ln_s2_b   = (const float*)d_in[4];
    const float* rsa_qkv_w = (const float*)d_in[5];
    const float* rsa_dw_w  = (const float*)d_in[6];
    const float* rsa_proj_w= (const float*)d_in[7];
    const float* rsa_temp  = (const float*)d_in[8];
    const float* ffs_in_w  = (const float*)d_in[9];
    const float* ffs_dw_w  = (const float*)d_in[10];
    const float* ffs_out_w = (const float*)d_in[11];
    const float* ln_c0_w   = (const float*)d_in[12];
    const float* ln_c0_b   = (const float*)d_in[13];
    const float* ln_c2_w   = (const float*)d_in[14];
    const float* ln_c2_b   = (const float*)d_in[15];
    const float* gsa_qkv_w = (const float*)d_in[16];
    const float* gsa_dw_w  = (const float*)d_in[17];
    const float* gsa_proj_w= (const float*)d_in[18];
    const float* gsa_temp  = (const float*)d_in[19];
    const float* ffc_in_w  = (const float*)d_in[20];
    const float* ffc_dw_w  = (const float*)d_in[21];
    const float* ffc_out_w = (const float*)d_in[22];
    float* outp = (float*)d_out;

    float *bufR, *bufX, *bufG, *attnb, *partb, *Mb;
    __half *big1, *big2;
    cudaGetSymbolAddress((void**)&bufR,  g_bufR);
    cudaGetSymbolAddress((void**)&bufX,  g_bufX);
    cudaGetSymbolAddress((void**)&bufG,  g_bufG);
    cudaGetSymbolAddress((void**)&big1,  g_big1);
    cudaGetSymbolAddress((void**)&big2,  g_big2);
    cudaGetSymbolAddress((void**)&attnb, g_attn);
    cudaGetSymbolAddress((void**)&partb, g_part);
    cudaGetSymbolAddress((void**)&Mb,    g_M);

    // convtc: X(17408) + BFx2(4096) + mu/rs(512) + sg/sb(256) = 22272 floats = 89088 B
    const int ctc_smem = (256 * XSTR + 4096 + 256 + 256 + 128 + 128) * (int)sizeof(float);
    const int cg_smem  = (128 * XSTR + 2048) * (int)sizeof(float);   // 43008
    const int rsa_smem = (4 * 64 * WSTR + 64) * (int)sizeof(float);
    cudaFuncSetAttribute(convtc_kernel, cudaFuncAttributeMaxDynamicSharedMemorySize, ctc_smem);
    cudaFuncSetAttribute(convgate_kernel, cudaFuncAttributeMaxDynamicSharedMemorySize, cg_smem);
    cudaFuncSetAttribute(rsa_attn_kernel, cudaFuncAttributeMaxDynamicSharedMemorySize, rsa_smem);

    // ---- stage 1: RSA + spatial FFN ----
    convtc_kernel<<<dim3(64, 1, Bn), 256, ctc_smem>>>(x, nullptr, ln_s0_w, ln_s0_b, rsa_qkv_w, big1, 192, 4);
    dwconv_kernel<<<dim3(8, 192, Bn), 256>>>(big1, rsa_dw_w, big2, 192);
    rsa_attn_kernel<<<Bn * 256, 256, rsa_smem>>>(big2, rsa_proj_w, bufR, rsa_temp);
    convtc_kernel<<<dim3(64, 1, Bn), 256, ctc_smem>>>(bufR, x, ln_s2_w, ln_s2_b, ffs_in_w, big1, 340, 0);
    dwconv_kernel<<<dim3(8, 340, Bn), 256>>>(big1, ffs_dw_w, big2, 340);
    convgate_kernel<<<dim3(128, 1, Bn), 256, cg_smem>>>(big2, ffs_out_w, bufX, bufR);

    // ---- stage 2: GSA + channel FFN ----
    convtc_kernel<<<dim3(64, 1, Bn), 256, ctc_smem>>>(bufX, nullptr, ln_c0_w, ln_c0_b, gsa_qkv_w, big1, 192, 0);
    dwconv_kernel<<<dim3(8, 192, Bn), 256>>>(big1, gsa_dw_w, big2, 192);
    gsa_attn_part<<<dim3(8, 64), 256>>>(big2, partb);
    gsa_attn_final<<<64, 128>>>(partb, attnb, gsa_temp);
    gsa_makeM<<<Bn, 256>>>(attnb, gsa_proj_w, Mb);
    gsa_mv_kernel<<<dim3(64, Bn), 256>>>(big2, Mb, bufG);
    convtc_kernel<<<dim3(64, 1, Bn), 256, ctc_smem>>>(bufG, bufX, ln_c2_w, ln_c2_b, ffc_in_w, big1, 340, 0);
    dwconv_kernel<<<dim3(8, 340, Bn), 256>>>(big1, ffc_dw_w, big2, 340);
    convgate_kernel<<<dim3(128, 1, Bn), 256, cg_smem>>>(big2, ffc_out_w, outp, bufG);
}

// round 16
// speedup vs baseline: 1.2214x; 1.0374x over previous
#include <cuda_runtime.h>
#include <cuda_fp16.h>
#include <math.h>
#include <stdint.h>

#define HW    16384
#define Bn    8
#define HIDn  170
#define XSTR  68
#define RST   72     // halfs per RSA smem row (144B, conflict-free for ldsm)

// ---------------- scratch (static device memory) ----------------
__device__ float  g_bufR[Bn * 64 * HW];
__device__ float  g_bufX[Bn * 64 * HW];
__device__ float  g_bufG[Bn * 64 * HW];
__device__ __half g_big1[Bn * 340 * HW];
__device__ __half g_big2[Bn * 340 * HW];
__device__ float  g_attn[Bn * 8 * 64];
__device__ float  g_part[64 * 8 * 80];
__device__ float  g_M[Bn * 64 * 64];

__device__ __forceinline__ float gelu_f(float x) {
    return 0.5f * x * (1.0f + erff(x * 0.70710678118654752f));
}
__device__ __forceinline__ uint16_t f16b(float x) {
    uint16_t r; asm("cvt.rn.f16.f32 %0, %1;" : "=h"(r) : "f"(x)); return r;
}
__device__ __forceinline__ uint32_t pk2(uint16_t lo, uint16_t hi) {
    return (uint32_t)lo | ((uint32_t)hi << 16);
}
__device__ __forceinline__ void fsplit(float v, uint16_t& h, uint16_t& l) {
    h = f16b(v);
    float hf; asm("cvt.f32.f16 %0, %1;" : "=f"(hf) : "h"(h));
    l = f16b(v - hf);
}
__device__ __forceinline__ void ldsm4(uint32_t* a, uint32_t addr) {
    asm volatile("ldmatrix.sync.aligned.m8n8.x4.shared.b16 {%0,%1,%2,%3}, [%4];"
        : "=r"(a[0]), "=r"(a[1]), "=r"(a[2]), "=r"(a[3]) : "r"(addr));
}
__device__ __forceinline__ void mma_f16(float* d, const uint32_t* a, uint32_t b0, uint32_t b1) {
    asm volatile("mma.sync.aligned.m16n8k16.row.col.f32.f16.f16.f32 "
        "{%0,%1,%2,%3}, {%4,%5,%6,%7}, {%8,%9}, {%0,%1,%2,%3};"
        : "+f"(d[0]), "+f"(d[1]), "+f"(d[2]), "+f"(d[3])
        : "r"(a[0]), "r"(a[1]), "r"(a[2]), "r"(a[3]), "r"(b0), "r"(b1));
}

// =================================================================
// LN-fused tensor-core conv1x1 (Cin=64, fp32 in), 2-term fp16,
// fp16 output. 256-px tiles, 2 CTAs/SM, double-buffered W staging.
// (unchanged from round 15 best)
// =================================================================
__global__ void __launch_bounds__(256, 2)
convtc_kernel(const float* __restrict__ in, const float* __restrict__ addp,
              const float* __restrict__ lnw, const float* __restrict__ lnb,
              const float* __restrict__ wt, __half* __restrict__ out,
              int Cout, int shift)
{
    extern __shared__ float sm[];
    float* Xh   = sm;
    uint2* BF   = (uint2*)(sm + 256 * XSTR);
    float* mu_s = sm + 256 * XSTR + 4096;
    float* rs_s = mu_s + 256;
    float* sg_s = rs_s + 256;
    float* sb_s = sg_s + 128;

    int b = blockIdx.z, p0 = blockIdx.x * 256;
    int tid = threadIdx.x, warp = tid >> 5, lane = tid & 31;
    const float* inb = in + (size_t)b * 64 * HW;
    const float* adb = addp ? addp + (size_t)b * 64 * HW : nullptr;

    int p = p0 + tid, ip = p;
    if (shift) {
        int hh = ((p >> 7) + shift) & 127, ww = ((p & 127) + shift) & 127;
        ip = (hh << 7) | ww;
    }
    float s_sum = 0.f, s_sq = 0.f;
    char* xrow = (char*)Xh + tid * 272;
    #pragma unroll
    for (int j8 = 0; j8 < 8; j8++) {
        uint16_t hb[8], lb[8];
        #pragma unroll
        for (int jj = 0; jj < 8; jj++) {
            int c = j8 * 8 + jj;
            float v = inb[(size_t)c * HW + ip];
            if (adb) v += adb[(size_t)c * HW + ip];
            s_sum += v; s_sq += v * v;
            fsplit(v, hb[jj], lb[jj]);
        }
        *(uint4*)(xrow + j8 * 16) =
            make_uint4(pk2(hb[0], hb[1]), pk2(hb[2], hb[3]), pk2(hb[4], hb[5]), pk2(hb[6], hb[7]));
        *(uint4*)(xrow + 144 + j8 * 16) =
            make_uint4(pk2(lb[0], lb[1]), pk2(lb[2], lb[3]), pk2(lb[4], lb[5]), pk2(lb[6], lb[7]));
    }
    {
        float m = s_sum * 0.015625f;
        float var = s_sq * 0.015625f - m * m;
        mu_s[tid] = m;
        rs_s[tid] = rsqrtf(fmaxf(var, 0.f) + 1e-5f);
    }

    int ntile = (Cout + 63) >> 6;
    #define STAGE_W(tt, sl)                                                              \
    {                                                                                    \
        int o0s = (tt) << 6;                                                             \
        uint2* bfs = BF + (size_t)(sl) * 1024;                                           \
        _Pragma("unroll")                                                                \
        for (int i = 0; i < 4; i++) {                                                    \
            int e = i * 256 + tid;                                                       \
            int kb = e >> 8, rem = e & 255;                                              \
            int n8 = rem >> 5, ln2 = rem & 31;                                           \
            int g = ln2 >> 2, t2 = ln2 & 3;                                              \
            int og = o0s + n8 * 8 + g;                                                   \
            int kbase = kb * 16;                                                         \
            float w0 = 0.f, w1 = 0.f, w2 = 0.f, w3 = 0.f;                                \
            if (og < Cout) {                                                             \
                const float* wr = wt + (size_t)og * 64 + kbase;                          \
                w0 = wr[2 * t2]     * lnw[kbase + 2 * t2];                               \
                w1 = wr[2 * t2 + 1] * lnw[kbase + 2 * t2 + 1];                           \
                w2 = wr[2 * t2 + 8] * lnw[kbase + 2 * t2 + 8];                           \
                w3 = wr[2 * t2 + 9] * lnw[kbase + 2 * t2 + 9];                           \
            }                                                                            \
            bfs[(kb * 8 + n8) * 32 + ln2] =                                              \
                make_uint2(pk2(f16b(w0), f16b(w1)), pk2(f16b(w2), f16b(w3)));            \
        }                                                                                \
        if (tid < 64) {                                                                  \
            float sg = 0.f, sb2 = 0.f;                                                   \
            int og = o0s + tid;                                                          \
            if (og < Cout) {                                                             \
                const float* wr = wt + (size_t)og * 64;                                  \
                _Pragma("unroll 8")                                                      \
                for (int k = 0; k < 64; k++) { sg += wr[k] * lnw[k]; sb2 += wr[k] * lnb[k]; } \
            }                                                                            \
            sg_s[(sl) * 64 + tid] = sg; sb_s[(sl) * 64 + tid] = sb2;                     \
        }                                                                                \
    }

    STAGE_W(0, 0);
    __syncthreads();

    for (int t = 0; t < ntile; t++) {
        int slot = t & 1;
        int o0 = t << 6;
        float accD[2][8][4] = {};
        uint32_t xbase = (uint32_t)__cvta_generic_to_shared(Xh);
        int r = lane & 7, madd8 = (lane >> 3) & 1, gsel = lane >> 4;
        uint32_t abase = xbase + (warp * 32 + r + madd8 * 8) * 272 + gsel * 16;
        const uint2* bfb = BF + (size_t)slot * 1024;
        #pragma unroll
        for (int kb = 0; kb < 4; kb++) {
            uint32_t Ah0[4], Ah1[4], Al0[4], Al1[4];
            uint32_t ah = abase + kb * 32;
            ldsm4(Ah0, ah);
            ldsm4(Ah1, ah + 16 * 272);
            ldsm4(Al0, ah + 144);
            ldsm4(Al1, ah + 144 + 16 * 272);
            const uint2* bfk = bfb + (size_t)kb * 8 * 32;
            #pragma unroll
            for (int n8 = 0; n8 < 8; n8++) {
                uint2 bv = bfk[n8 * 32 + lane];
                mma_f16(accD[0][n8], Ah0, bv.x, bv.y);
                mma_f16(accD[0][n8], Al0, bv.x, bv.y);
                mma_f16(accD[1][n8], Ah1, bv.x, bv.y);
                mma_f16(accD[1][n8], Al1, bv.x, bv.y);
            }
        }
        if (t + 1 < ntile) STAGE_W(t + 1, 1 - slot);
        int gq = lane >> 2, oq = (lane & 3) * 2;
        const float* sgp = sg_s + slot * 64;
        const float* sbp = sb_s + slot * 64;
        #pragma unroll
        for (int tt = 0; tt < 2; tt++) {
            int pxa = warp * 32 + tt * 16 + gq;
            int pxb = pxa + 8;
            float mua = mu_s[pxa], rsa_ = rs_s[pxa];
            float mub = mu_s[pxb], rsb = rs_s[pxb];
            #pragma unroll
            for (int n8 = 0; n8 < 8; n8++) {
                #pragma unroll
                for (int q = 0; q < 2; q++) {
                    int ol = n8 * 8 + oq + q;
                    int og = o0 + ol;
                    if (og < Cout) {
                        float sg = sgp[ol], sb = sbp[ol];
                        float v0 = rsa_ * (accD[tt][n8][q]     - mua * sg) + sb;
                        float v1 = rsb  * (accD[tt][n8][q + 2] - mub * sg) + sb;
                        size_t obase = ((size_t)b * Cout + og) * HW + p0;
                        out[obase + pxa] = __float2half(v0);
                        out[obase + pxb] = __float2half(v1);
                    }
                }
            }
        }
        __syncthreads();
    }
    #undef STAGE_W
}

// =================================================================
// gated tensor-core conv (unchanged from round 15)
// =================================================================
__global__ void __launch_bounds__(256, 3)
convgate_kernel(const __half* __restrict__ in, const float* __restrict__ wt,
                float* __restrict__ out, const float* __restrict__ resid)
{
    extern __shared__ float sm[];
    float* Xh = sm;
    uint2* BF = (uint2*)(sm + 128 * XSTR);

    int b = blockIdx.z, p0 = blockIdx.x * 128;
    int tid = threadIdx.x, warp = tid >> 5, lane = tid & 31;
    int px = tid & 127, half = tid >> 7;
    int ip = p0 + px;
    const __half* inb = in + (size_t)b * 340 * HW;

    float acc[8][4] = {};
    const int kbs16[3] = {4, 4, 3};
    for (int ch = 0; ch < 3; ch++) {
        if (ch) __syncthreads();
        int c0 = ch * 64;
        int nkb = kbs16[ch];
        char* xrow = (char*)Xh + px * 272;
        #pragma unroll
        for (int j8 = 0; j8 < 4; j8++) {
            uint16_t hb[8], lb[8];
            #pragma unroll
            for (int jj = 0; jj < 8; jj++) {
                int c = c0 + half * 32 + j8 * 8 + jj;
                float v = 0.f;
                if (c < HIDn) {
                    float a = __half2float(inb[(size_t)c * HW + ip]);
                    float g = __half2float(inb[(size_t)(c + HIDn) * HW + ip]);
                    v = gelu_f(a) * g;
                }
                fsplit(v, hb[jj], lb[jj]);
            }
            *(uint4*)(xrow + half * 64 + j8 * 16) =
                make_uint4(pk2(hb[0], hb[1]), pk2(hb[2], hb[3]), pk2(hb[4], hb[5]), pk2(hb[6], hb[7]));
            *(uint4*)(xrow + 144 + half * 64 + j8 * 16) =
                make_uint4(pk2(lb[0], lb[1]), pk2(lb[2], lb[3]), pk2(lb[4], lb[5]), pk2(lb[6], lb[7]));
        }
        int tot = nkb * 256;
        for (int e = tid; e < tot; e += 256) {
            int kb = e >> 8, rem = e & 255;
            int n8 = rem >> 5, ln2 = rem & 31;
            int g = ln2 >> 2, t2 = ln2 & 3;
            int o = n8 * 8 + g;
            int kbase = c0 + kb * 16;
            int k0 = kbase + 2 * t2, k1 = k0 + 1, k2 = kbase + 2 * t2 + 8, k3 = k2 + 1;
            float w0 = (k0 < HIDn) ? wt[(size_t)o * HIDn + k0] : 0.f;
            float w1 = (k1 < HIDn) ? wt[(size_t)o * HIDn + k1] : 0.f;
            float w2 = (k2 < HIDn) ? wt[(size_t)o * HIDn + k2] : 0.f;
            float w3 = (k3 < HIDn) ? wt[(size_t)o * HIDn + k3] : 0.f;
            BF[(kb * 8 + n8) * 32 + ln2] =
                make_uint2(pk2(f16b(w0), f16b(w1)), pk2(f16b(w2), f16b(w3)));
        }
        __syncthreads();
        uint32_t xbase = (uint32_t)__cvta_generic_to_shared(Xh);
        int r = lane & 7, madd8 = (lane >> 3) & 1, gsel = lane >> 4;
        uint32_t abase = xbase + (warp * 16 + r + madd8 * 8) * 272 + gsel * 16;
        #pragma unroll
        for (int kb = 0; kb < 4; kb++) {
            if (kb >= nkb) break;
            uint32_t Ah0[4], Al0[4];
            uint32_t ah = abase + kb * 32;
            ldsm4(Ah0, ah);
            ldsm4(Al0, ah + 144);
            const uint2* bfk = BF + (size_t)kb * 8 * 32;
            #pragma unroll
            for (int n8 = 0; n8 < 8; n8++) {
                uint2 bv = bfk[n8 * 32 + lane];
                mma_f16(acc[n8], Ah0, bv.x, bv.y);
                mma_f16(acc[n8], Al0, bv.x, bv.y);
            }
        }
    }
    int gq = lane >> 2, oq = (lane & 3) * 2;
    int pxa = warp * 16 + gq, pxb = pxa + 8;
    #pragma unroll
    for (int n8 = 0; n8 < 8; n8++) {
        #pragma unroll
        for (int q = 0; q < 2; q++) {
            int og = n8 * 8 + oq + q;
            size_t obase = ((size_t)b * 64 + og) * HW + p0;
            out[obase + pxa] = acc[n8][q]     + resid[obase + pxa];
            out[obase + pxb] = acc[n8][q + 2] + resid[obase + pxb];
        }
    }
}

// ---------------- depthwise 3x3 conv, fp16 I/O (unchanged) ----------------
__global__ void dwconv_kernel(const __half* __restrict__ in, const float* __restrict__ wt,
                              __half* __restrict__ out, int Ch)
{
    int c = blockIdx.y, b = blockIdx.z;
    int p = (blockIdx.x * 256 + threadIdx.x) << 3;
    int h = p >> 7, w0 = p & 127;
    const __half* ib = in + ((size_t)b * Ch + c) * HW;
    const float* wc = wt + c * 9;
    float acc[8] = {0.f,0.f,0.f,0.f,0.f,0.f,0.f,0.f};
    #pragma unroll
    for (int dy = -1; dy <= 1; dy++) {
        int hh = h + dy;
        if ((unsigned)hh > 127u) continue;
        const __half* row = ib + (hh << 7);
        uint4 mraw = *(const uint4*)(row + w0);
        const __half2* m2 = (const __half2*)&mraw;
        float r[10];
        r[0] = (w0 > 0)   ? __half2float(row[w0 - 1]) : 0.f;
        #pragma unroll
        for (int k = 0; k < 4; k++) {
            float2 f = __half22float2(m2[k]);
            r[1 + 2 * k] = f.x; r[2 + 2 * k] = f.y;
        }
        r[9] = (w0 < 120) ? __half2float(row[w0 + 8]) : 0.f;
        float wa = wc[(dy + 1) * 3 + 0], wb = wc[(dy + 1) * 3 + 1], wcc = wc[(dy + 1) * 3 + 2];
        #pragma unroll
        for (int j = 0; j < 8; j++)
            acc[j] += wa * r[j] + wb * r[j + 1] + wcc * r[j + 2];
    }
    __half2 o2[4];
    #pragma unroll
    for (int k = 0; k < 4; k++) o2[k] = __floats2half2_rn(acc[2 * k], acc[2 * k + 1]);
    *(uint4*)(out + ((size_t)b * Ch + c) * HW + p) = *(uint4*)o2;
}

// =================================================================
// RSA window attention — mma.sync fp16 rewrite (2-term splits).
// GEMM1: attn[c,d] = q[c,p]·kn[d,p]; GEMM2: out[d,p] = attnT·v;
// GEMM3: y[o,p] = Pw·out. q/k/v exact fp16; all derived 2-term.
// smem: 9 rows-regions [64][72] halfs + BFh/BFl frag bufs + inv/nrm
// =================================================================
__global__ void __launch_bounds__(256, 2)
rsa_attn_kernel(const __half* __restrict__ qkv, const float* __restrict__ pw,
                float* __restrict__ out, const float* __restrict__ temp)
{
    extern __shared__ float sm[];
    __half* Sq   = (__half*)sm;
    __half* Sk   = Sq   + 64 * RST;
    __half* Sv   = Sk   + 64 * RST;
    __half* Sath = Sv   + 64 * RST;
    __half* Satl = Sath + 64 * RST;
    __half* So2h = Satl + 64 * RST;
    __half* So2l = So2h + 64 * RST;
    __half* Spwh = So2l + 64 * RST;
    __half* Spwl = Spwh + 64 * RST;
    uint2*  BFh  = (uint2*)(Spwl + 64 * RST);
    uint2*  BFl  = BFh + 1024;
    float*  inv  = (float*)(BFl + 1024);   // [64]
    float*  nrm  = inv + 64;               // [128]

    int blk = blockIdx.x;
    int b = blk >> 8, win = blk & 255;
    int wy = win >> 4, wx = win & 15;
    int tid = threadIdx.x, warp = tid >> 5, lane = tid & 31;
    size_t qbase = (size_t)b * 192 * HW;

    // ---- stage q,k,v (vectorized fp16 copies; p = row*8+col) ----
    for (int e = tid; e < 512; e += 256) {
        int c = e >> 3, pr = e & 7;
        size_t gp = qbase + (size_t)c * HW + (((wy << 3) + pr) << 7) + (wx << 3);
        *(uint4*)(Sq + c * RST + pr * 8) = *(const uint4*)(qkv + gp);
        *(uint4*)(Sk + c * RST + pr * 8) = *(const uint4*)(qkv + gp + (size_t)64 * HW);
        *(uint4*)(Sv + c * RST + pr * 8) = *(const uint4*)(qkv + gp + (size_t)128 * HW);
    }
    // ---- stage Pw (2-term) ----
    for (int e = tid; e < 4096; e += 256) {
        uint16_t h, l;
        fsplit(pw[e], h, l);
        ((uint16_t*)Spwh)[(e >> 6) * RST + (e & 63)] = h;
        ((uint16_t*)Spwl)[(e >> 6) * RST + (e & 63)] = l;
    }
    __syncthreads();
    // ---- norms ----
    if (tid < 128) {
        const __half* s = (tid < 64) ? Sq : Sk;
        int p = tid & 63;
        float n = 0.f;
        #pragma unroll 8
        for (int c = 0; c < 64; c++) {
            float v = __half2float(s[c * RST + p]);
            n += v * v;
        }
        nrm[tid] = n;
    }
    __syncthreads();
    if (tid < 64) {
        float dq = fmaxf(sqrtf(nrm[tid]), 1e-12f);
        float dk = fmaxf(sqrtf(nrm[64 + tid]), 1e-12f);
        inv[tid] = 1.0f / (dq * dk);
    }
    __syncthreads();
    // ---- pack kn = k*inv (2-term) into B frags: n=d, k=p ----
    for (int e = tid; e < 1024; e += 256) {
        int kb = e >> 8, rem = e & 255;
        int n8 = rem >> 5, ln2 = rem & 31;
        int g = ln2 >> 2, t2 = ln2 & 3;
        int d = n8 * 8 + g;
        int pA = kb * 16 + 2 * t2;
        float v0 = __half2float(Sk[d * RST + pA])     * inv[pA];
        float v1 = __half2float(Sk[d * RST + pA + 1]) * inv[pA + 1];
        float v2 = __half2float(Sk[d * RST + pA + 8]) * inv[pA + 8];
        float v3 = __half2float(Sk[d * RST + pA + 9]) * inv[pA + 9];
        uint16_t h0, l0, h1, l1, h2, l2, h3, l3;
        fsplit(v0, h0, l0); fsplit(v1, h1, l1);
        fsplit(v2, h2, l2); fsplit(v3, h3, l3);
        BFh[e] = make_uint2(pk2(h0, h1), pk2(h2, h3));
        BFl[e] = make_uint2(pk2(l0, l1), pk2(l2, l3));
    }
    __syncthreads();
    int mi = warp & 3, nj0 = (warp >> 2) * 4;
    int r = lane & 7, madd8 = (lane >> 3) & 1, gsel = lane >> 4;
    int gq = lane >> 2, oq = (lane & 3) * 2;
    float ts = temp[0];
    // ---- GEMM1: attn frags ----
    {
        float acc[4][4] = {};
        uint32_t qb32 = (uint32_t)__cvta_generic_to_shared(Sq);
        uint32_t abase = qb32 + (mi * 16 + r + madd8 * 8) * 144 + gsel * 16;
        #pragma unroll
        for (int kb = 0; kb < 4; kb++) {
            uint32_t A[4];
            ldsm4(A, abase + kb * 32);
            #pragma unroll
            for (int j = 0; j < 4; j++) {
                int idx = (kb * 8 + nj0 + j) * 32 + lane;
                uint2 bh = BFh[idx];
                uint2 bl = BFl[idx];
                mma_f16(acc[j], A, bh.x, bh.y);
                mma_f16(acc[j], A, bl.x, bl.y);
            }
        }
        // relu, split, write attnT [d][c]
        #pragma unroll
        for (int j = 0; j < 4; j++) {
            #pragma unroll
            for (int q = 0; q < 4; q++) {
                int c = mi * 16 + gq + ((q >= 2) ? 8 : 0);
                int d = (nj0 + j) * 8 + oq + (q & 1);
                float a = fmaxf(0.f, ts * acc[j][q]);
                uint16_t h, l;
                fsplit(a, h, l);
                ((uint16_t*)Sath)[d * RST + c] = h;
                ((uint16_t*)Satl)[d * RST + c] = l;
            }
        }
    }
    __syncthreads();
    // ---- pack v into B frags: n=p, k=c ----
    for (int e = tid; e < 1024; e += 256) {
        int kb = e >> 8, rem = e & 255;
        int n8 = rem >> 5, ln2 = rem & 31;
        int g = ln2 >> 2, t2 = ln2 & 3;
        int p = n8 * 8 + g;
        int c0 = kb * 16 + 2 * t2;
        const uint16_t* vv = (const uint16_t*)Sv;
        BFh[e] = make_uint2(pk2(vv[c0 * RST + p], vv[(c0 + 1) * RST + p]),
                            pk2(vv[(c0 + 8) * RST + p], vv[(c0 + 9) * RST + p]));
    }
    __syncthreads();
    // ---- GEMM2: out[d][p] ----
    {
        float acc[4][4] = {};
        uint32_t ah32 = (uint32_t)__cvta_generic_to_shared(Sath);
        uint32_t al32 = (uint32_t)__cvta_generic_to_shared(Satl);
        uint32_t abh = ah32 + (mi * 16 + r + madd8 * 8) * 144 + gsel * 16;
        uint32_t abl = al32 + (mi * 16 + r + madd8 * 8) * 144 + gsel * 16;
        #pragma unroll
        for (int kb = 0; kb < 4; kb++) {
            uint32_t Ah[4], Al[4];
            ldsm4(Ah, abh + kb * 32);
            ldsm4(Al, abl + kb * 32);
            #pragma unroll
            for (int j = 0; j < 4; j++) {
                uint2 bv = BFh[(kb * 8 + nj0 + j) * 32 + lane];
                mma_f16(acc[j], Ah, bv.x, bv.y);
                mma_f16(acc[j], Al, bv.x, bv.y);
            }
        }
        // write out2 [d][p] 2-term
        #pragma unroll
        for (int j = 0; j < 4; j++) {
            #pragma unroll
            for (int q = 0; q < 4; q++) {
                int d = mi * 16 + gq + ((q >= 2) ? 8 : 0);
                int p = (nj0 + j) * 8 + oq + (q & 1);
                uint16_t h, l;
                fsplit(acc[j][q], h, l);
                ((uint16_t*)So2h)[d * RST + p] = h;
                ((uint16_t*)So2l)[d * RST + p] = l;
            }
        }
    }
    __syncthreads();
    // ---- pack out2 into B frags: n=p, k=d (2-term) ----
    for (int e = tid; e < 1024; e += 256) {
        int kb = e >> 8, rem = e & 255;
        int n8 = rem >> 5, ln2 = rem & 31;
        int g = ln2 >> 2, t2 = ln2 & 3;
        int p = n8 * 8 + g;
        int d0 = kb * 16 + 2 * t2;
        const uint16_t* oh = (const uint16_t*)So2h;
        const uint16_t* ol = (const uint16_t*)So2l;
        BFh[e] = make_uint2(pk2(oh[d0 * RST + p], oh[(d0 + 1) * RST + p]),
                            pk2(oh[(d0 + 8) * RST + p], oh[(d0 + 9) * RST + p]));
        BFl[e] = make_uint2(pk2(ol[d0 * RST + p], ol[(d0 + 1) * RST + p]),
                            pk2(ol[(d0 + 8) * RST + p], ol[(d0 + 9) * RST + p]));
    }
    __syncthreads();
    // ---- GEMM3: y[o][p] = Pw·out ----
    {
        float acc[4][4] = {};
        uint32_t ph32 = (uint32_t)__cvta_generic_to_shared(Spwh);
        uint32_t pl32 = (uint32_t)__cvta_generic_to_shared(Spwl);
        uint32_t abh = ph32 + (mi * 16 + r + madd8 * 8) * 144 + gsel * 16;
        uint32_t abl = pl32 + (mi * 16 + r + madd8 * 8) * 144 + gsel * 16;
        #pragma unroll
        for (int kb = 0; kb < 4; kb++) {
            uint32_t Ah[4], Al[4];
            ldsm4(Ah, abh + kb * 32);
            ldsm4(Al, abl + kb * 32);
            #pragma unroll
            for (int j = 0; j < 4; j++) {
                int idx = (kb * 8 + nj0 + j) * 32 + lane;
                uint2 bh = BFh[idx];
                uint2 bl = BFl[idx];
                mma_f16(acc[j], Ah, bh.x, bh.y);
                mma_f16(acc[j], Ah, bl.x, bl.y);
                mma_f16(acc[j], Al, bh.x, bh.y);
            }
        }
        // store with inverse roll (+4,+4), fp32
        size_t obase = (size_t)b * 64 * HW;
        #pragma unroll
        for (int j = 0; j < 4; j++) {
            #pragma unroll
            for (int q = 0; q < 4; q++) {
                int o = mi * 16 + gq + ((q >= 2) ? 8 : 0);
                int p = (nj0 + j) * 8 + oq + (q & 1);
                int gh = (((wy << 3) + (p >> 3)) + 4) & 127;
                int gw = (((wx << 3) + (p & 7)) + 4) & 127;
                out[obase + (size_t)o * HW + (gh << 7) + gw] = acc[j][q];
            }
        }
    }
}

// ---------------- GSA: partial Gram sums (unchanged) ---------------------------
__global__ void gsa_attn_part(const __half* __restrict__ qkv, float* __restrict__ part)
{
    __shared__ float red[8][80];
    int bh = blockIdx.y;
    int b = bh >> 3, hd = bh & 7;
    int chunk = blockIdx.x;
    int tid = threadIdx.x;
    const __half* qb = qkv + ((size_t)b * 192 + hd * 8) * HW;
    const __half* kb = qkv + ((size_t)b * 192 + 64 + hd * 8) * HW;
    float dot[8][8] = {};
    float qn[8] = {}, kn[8] = {};
    int n0 = chunk * 2048;
    for (int n = n0 + tid; n < n0 + 2048; n += 256) {
        float qv[8], kv[8];
        #pragma unroll
        for (int i = 0; i < 8; i++) {
            qv[i] = __half2float(qb[i * HW + n]);
            kv[i] = __half2float(kb[i * HW + n]);
        }
        #pragma unroll
        for (int i = 0; i < 8; i++) { qn[i] += qv[i] * qv[i]; kn[i] += kv[i] * kv[i]; }
        #pragma unroll
        for (int i = 0; i < 8; i++)
            #pragma unroll
            for (int j = 0; j < 8; j++) dot[i][j] += qv[i] * kv[j];
    }
    int lane = tid & 31, w = tid >> 5;
    #pragma unroll
    for (int i = 0; i < 8; i++)
        #pragma unroll
        for (int j = 0; j < 8; j++) {
            float v = dot[i][j];
            #pragma unroll
            for (int off = 16; off; off >>= 1) v += __shfl_xor_sync(0xffffffffu, v, off);
            if (lane == 0) red[w][i * 8 + j] = v;
        }
    #pragma unroll
    for (int i = 0; i < 8; i++) {
        float v = qn[i];
        #pragma unroll
        for (int off = 16; off; off >>= 1) v += __shfl_xor_sync(0xffffffffu, v, off);
        if (lane == 0) red[w][64 + i] = v;
        float u = kn[i];
        #pragma unroll
        for (int off = 16; off; off >>= 1) u += __shfl_xor_sync(0xffffffffu, u, off);
        if (lane == 0) red[w][72 + i] = u;
    }
    __syncthreads();
    if (tid < 80) {
        float s = 0.f;
        #pragma unroll
        for (int w2 = 0; w2 < 8; w2++) s += red[w2][tid];
        part[((size_t)bh * 8 + chunk) * 80 + tid] = s;
    }
}

// ---------------- GSA: merged finalize + proj-fold (one kernel) ----------------
__global__ void gsa_finalM(const float* __restrict__ part, const float* __restrict__ pw,
                           float* __restrict__ M, const float* __restrict__ temp)
{
    __shared__ float fin[8][80];
    __shared__ float at[512];
    int b = blockIdx.x, tid = threadIdx.x;
    for (int e = tid; e < 640; e += 256) {
        int hd = e / 80, idx = e - hd * 80;
        int bh = b * 8 + hd;
        float s = 0.f;
        #pragma unroll
        for (int c = 0; c < 8; c++) s += part[((size_t)bh * 8 + c) * 80 + idx];
        fin[hd][idx] = s;
    }
    __syncthreads();
    for (int e = tid; e < 512; e += 256) {
        int hd = e >> 6, c = (e >> 3) & 7, d = e & 7;
        float nq = fmaxf(sqrtf(fin[hd][64 + c]), 1e-12f);
        float nk = fmaxf(sqrtf(fin[hd][72 + d]), 1e-12f);
        at[e] = fmaxf(0.f, temp[0] * fin[hd][c * 8 + d] / (nq * nk));
    }
    __syncthreads();
    for (int t = 0; t < 16; t++) {
        int e = t * 256 + tid;
        int o = e >> 6, chp = e & 63;
        int hd = chp >> 3, d = chp & 7;
        float s = 0.f;
        #pragma unroll
        for (int c = 0; c < 8; c++)
            s += pw[(size_t)o * 64 + c * 8 + hd] * at[hd * 64 + c * 8 + d];
        M[(size_t)b * 4096 + e] = s;
    }
}

// ---------------- GSA: out = M @ v (unchanged) ------------------------------
__global__ void gsa_mv_kernel(const __half* __restrict__ qkv, const float* __restrict__ M,
                              float* __restrict__ out)
{
    __shared__ float Ms[4096];
    int b = blockIdx.y, tid = threadIdx.x;
    for (int e = tid; e < 4096; e += 256) Ms[e] = M[(size_t)b * 4096 + e];
    __syncthreads();
    int n = blockIdx.x * 256 + tid;
    const __half* vb = qkv + ((size_t)b * 192 + 128) * HW + n;
    float* ob = out + (size_t)b * 64 * HW + n;
    float vv[64];
    #pragma unroll
    for (int c = 0; c < 64; c++) vv[c] = __half2float(vb[(size_t)c * HW]);
    #pragma unroll
    for (int og = 0; og < 8; og++) {
        float acc[8] = {0.f,0.f,0.f,0.f,0.f,0.f,0.f,0.f};
        #pragma unroll
        for (int c = 0; c < 64; c++) {
            float v = vv[c];
            #pragma unroll
            for (int j = 0; j < 8; j++) acc[j] += Ms[(og * 8 + j) * 64 + c] * v;
        }
        #pragma unroll
        for (int j = 0; j < 8; j++) ob[(size_t)(og * 8 + j) * HW] = acc[j];
    }
}

// ---------------- launch ---------------------------------------------------------
extern "C" void kernel_launch(void* const* d_in, const int* in_sizes, int n_in,
                              void* d_out, int out_size)
{
    const float* x         = (const float*)d_in[0];
    const float* ln_s0_w   = (const float*)d_in[1];
    const float* ln_s0_b   = (const float*)d_in[2];
    const float* ln_s2_w   = (const float*)d_in[3];
    const float* ln_s2_b   = (const float*)d_in[4];
    const float* rsa_qkv_w = (const float*)d_in[5];
    const float* rsa_dw_w  = (const float*)d_in[6];
    const float* rsa_proj_w= (const float*)d_in[7];
    const float* rsa_temp  = (const float*)d_in[8];
    const float* ffs_in_w  = (const float*)d_in[9];
    const float* ffs_dw_w  = (const float*)d_in[10];
    const float* ffs_out_w = (const float*)d_in[11];
    const float* ln_c0_w   = (const float*)d_in[12];
    const float* ln_c0_b   = (const float*)d_in[13];
    const float* ln_c2_w   = (const float*)d_in[14];
    const float* ln_c2_b   = (const float*)d_in[15];
    const float* gsa_qkv_w = (const float*)d_in[16];
    const float* gsa_dw_w  = (const float*)d_in[17];
    const float* gsa_proj_w= (const float*)d_in[18];
    const float* gsa_temp  = (const float*)d_in[19];
    const float* ffc_in_w  = (const float*)d_in[20];
    const float* ffc_dw_w  = (const float*)d_in[21];
    const float* ffc_out_w = (const float*)d_in[22];
    float* outp = (float*)d_out;

    float *bufR, *bufX, *bufG, *attnb, *partb, *Mb;
    __half *big1, *big2;
    cudaGetSymbolAddress((void**)&bufR,  g_bufR);
    cudaGetSymbolAddress((void**)&bufX,  g_bufX);
    cudaGetSymbolAddress((void**)&bufG,  g_bufG);
    cudaGetSymbolAddress((void**)&big1,  g_big1);
    cudaGetSymbolAddress((void**)&big2,  g_big2);
    cudaGetSymbolAddress((void**)&attnb, g_attn);
    cudaGetSymbolAddress((void**)&partb, g_part);
    cudaGetSymbolAddress((void**)&Mb,    g_M);

    const int ctc_smem = (256 * XSTR + 4096 + 256 + 256 + 128 + 128) * (int)sizeof(float);
    const int cg_smem  = (128 * XSTR + 2048) * (int)sizeof(float);
    // rsa: 9 * 64*72 halfs (82944B) + BFh/BFl (16384B) + inv/nrm (768B) = 100096 B
    const int rsa_smem = 100096;
    cudaFuncSetAttribute(convtc_kernel, cudaFuncAttributeMaxDynamicSharedMemorySize, ctc_smem);
    cudaFuncSetAttribute(convgate_kernel, cudaFuncAttributeMaxDynamicSharedMemorySize, cg_smem);
    cudaFuncSetAttribute(rsa_attn_kernel, cudaFuncAttributeMaxDynamicSharedMemorySize, rsa_smem);

    // ---- stage 1: RSA + spatial FFN ----
    convtc_kernel<<<dim3(64, 1, Bn), 256, ctc_smem>>>(x, nullptr, ln_s0_w, ln_s0_b, rsa_qkv_w, big1, 192, 4);
    dwconv_kernel<<<dim3(8, 192, Bn), 256>>>(big1, rsa_dw_w, big2, 192);
    rsa_attn_kernel<<<Bn * 256, 256, rsa_smem>>>(big2, rsa_proj_w, bufR, rsa_temp);
    convtc_kernel<<<dim3(64, 1, Bn), 256, ctc_smem>>>(bufR, x, ln_s2_w, ln_s2_b, ffs_in_w, big1, 340, 0);
    dwconv_kernel<<<dim3(8, 340, Bn), 256>>>(big1, ffs_dw_w, big2, 340);
    convgate_kernel<<<dim3(128, 1, Bn), 256, cg_smem>>>(big2, ffs_out_w, bufX, bufR);

    // ---- stage 2: GSA + channel FFN ----
    convtc_kernel<<<dim3(64, 1, Bn), 256, ctc_smem>>>(bufX, nullptr, ln_c0_w, ln_c0_b, gsa_qkv_w, big1, 192, 0);
    dwconv_kernel<<<dim3(8, 192, Bn), 256>>>(big1, gsa_dw_w, big2, 192);
    gsa_attn_part<<<dim3(8, 64), 256>>>(big2, partb);
    gsa_finalM<<<Bn, 256>>>(partb, gsa_proj_w, Mb, gsa_temp);
    gsa_mv_kernel<<<dim3(64, Bn), 256>>>(big2, Mb, bufG);
    convtc_kernel<<<dim3(64, 1, Bn), 256, ctc_smem>>>(bufG, bufX, ln_c2_w, ln_c2_b, ffc_in_w, big1, 340, 0);
    dwconv_kernel<<<dim3(8, 340, Bn), 256>>>(big1, ffc_dw_w, big2, 340);
    convgate_kernel<<<dim3(128, 1, Bn), 256, cg_smem>>>(big2, ffc_out_w, outp, bufG);
}